// round 1
// baseline (speedup 1.0000x reference)
#include <cuda_runtime.h>
#include <math.h>

// Problem constants
#define BB   128
#define TT   256
#define CC   384
#define HH   6
#define DD   64
#define NROWS (BB*TT)          // 32768
#define QKVW  (3*CC)           // 1152
#define FFN   (4*CC)           // 1536
#define LN_EPS 1e-5f
#define ATT_SCALE 0.05103103630798287f   // 384^-0.5

// ---------------------------------------------------------------------------
// Scratch (device globals; allocation is forbidden)
// ---------------------------------------------------------------------------
__device__ float g_xn  [(size_t)NROWS*CC];
__device__ float g_qkv [(size_t)NROWS*QKVW];
__device__ float g_o   [(size_t)NROWS*CC];
__device__ float g_x1  [(size_t)NROWS*CC];
__device__ float g_xn2 [(size_t)NROWS*CC];
__device__ float g_h   [(size_t)NROWS*FFN];
__device__ float g_wqkv[(size_t)CC*QKVW];

// ---------------------------------------------------------------------------
// Pack Wq/Wk/Wv [H,C,D] into one [C, 3*H*D] row-major matrix:
//   col = proj*384 + h*64 + d
// ---------------------------------------------------------------------------
__global__ void pack_w_kernel(const float* __restrict__ Wq,
                              const float* __restrict__ Wk,
                              const float* __restrict__ Wv,
                              float* __restrict__ out)
{
    int idx = blockIdx.x * 256 + threadIdx.x;
    if (idx >= CC * QKVW) return;
    int c    = idx / QKVW;
    int col  = idx % QKVW;
    int proj = col / CC;
    int hd   = col % CC;
    int h = hd >> 6, d = hd & 63;
    const float* W = (proj == 0) ? Wq : ((proj == 1) ? Wk : Wv);
    out[idx] = W[(size_t)h * CC * DD + (size_t)c * DD + d];
}

// ---------------------------------------------------------------------------
// LayerNorm: one block (128 threads) per row of 384
// ---------------------------------------------------------------------------
__global__ void __launch_bounds__(128) ln_kernel(const float* __restrict__ x,
                                                 const float* __restrict__ g,
                                                 const float* __restrict__ be,
                                                 float* __restrict__ out)
{
    const int row = blockIdx.x;
    const int tid = threadIdx.x;
    const float* xr = x + (size_t)row * CC;

    float v0 = xr[tid], v1 = xr[tid + 128], v2 = xr[tid + 256];
    float s  = v0 + v1 + v2;
    float sq = v0*v0 + v1*v1 + v2*v2;

    #pragma unroll
    for (int off = 16; off > 0; off >>= 1) {
        s  += __shfl_xor_sync(0xffffffffu, s,  off);
        sq += __shfl_xor_sync(0xffffffffu, sq, off);
    }
    __shared__ float ss[4], ssq[4];
    const int wid = tid >> 5, lane = tid & 31;
    if (lane == 0) { ss[wid] = s; ssq[wid] = sq; }
    __syncthreads();
    s  = ss[0]  + ss[1]  + ss[2]  + ss[3];
    sq = ssq[0] + ssq[1] + ssq[2] + ssq[3];

    const float mu  = s * (1.0f / CC);
    const float var = sq * (1.0f / CC) - mu * mu;
    const float inv = rsqrtf(var + LN_EPS);

    float* orow = out + (size_t)row * CC;
    orow[tid      ] = (v0 - mu) * inv * g[tid      ] + be[tid      ];
    orow[tid + 128] = (v1 - mu) * inv * g[tid + 128] + be[tid + 128];
    orow[tid + 256] = (v2 - mu) * inv * g[tid + 256] + be[tid + 256];
}

// ---------------------------------------------------------------------------
// SGEMM 128x128x8, 256 threads, 8x8 microtile.
//   C[N,M] = A[N,K] @ B[K,M]  (+ epilogue)
//   EPI 0: none   EPI 1: + bias[col] + res[row,col]   EPI 2: relu(+ bias[col])
// Requires N%128==0, M%128==0, K%8==0.
// ---------------------------------------------------------------------------
template <int EPI>
__global__ void __launch_bounds__(256) sgemm_kernel(
    const float* __restrict__ A, const float* __restrict__ B,
    float* __restrict__ C, int N, int K, int M,
    const float* __restrict__ bias, const float* __restrict__ res)
{
    __shared__ float As[8][128];
    __shared__ float Bs[8][132];

    const int tid = threadIdx.x;
    const int bx = blockIdx.x;   // column tile
    const int by = blockIdx.y;   // row tile

    const int rowA = tid >> 1;
    const int kA   = (tid & 1) * 4;
    const int kB   = tid >> 5;
    const int colB = (tid & 31) * 4;

    const float* Aptr = A + (size_t)(by * 128 + rowA) * K + kA;
    const float* Bptr = B + (size_t)kB * M + bx * 128 + colB;

    float acc[8][8];
    #pragma unroll
    for (int i = 0; i < 8; i++)
        #pragma unroll
        for (int j = 0; j < 8; j++) acc[i][j] = 0.0f;

    const int rb = (tid >> 4) * 8;
    const int cb = (tid & 15) * 8;

    for (int kt = 0; kt < K; kt += 8) {
        float4 a = *(const float4*)(Aptr + kt);
        float4 b = *(const float4*)(Bptr + (size_t)kt * M);
        As[kA + 0][rowA] = a.x;
        As[kA + 1][rowA] = a.y;
        As[kA + 2][rowA] = a.z;
        As[kA + 3][rowA] = a.w;
        *(float4*)&Bs[kB][colB] = b;
        __syncthreads();

        #pragma unroll
        for (int k = 0; k < 8; k++) {
            float4 a0 = *(const float4*)&As[k][rb];
            float4 a1 = *(const float4*)&As[k][rb + 4];
            float4 b0 = *(const float4*)&Bs[k][cb];
            float4 b1 = *(const float4*)&Bs[k][cb + 4];
            float ar[8] = {a0.x, a0.y, a0.z, a0.w, a1.x, a1.y, a1.z, a1.w};
            float br[8] = {b0.x, b0.y, b0.z, b0.w, b1.x, b1.y, b1.z, b1.w};
            #pragma unroll
            for (int i = 0; i < 8; i++)
                #pragma unroll
                for (int j = 0; j < 8; j++)
                    acc[i][j] = fmaf(ar[i], br[j], acc[i][j]);
        }
        __syncthreads();
    }

    const int row0 = by * 128 + rb;
    const int col0 = bx * 128 + cb;
    float bias_r[8];
    if (EPI != 0) {
        #pragma unroll
        for (int j = 0; j < 8; j++) bias_r[j] = bias[col0 + j];
    }
    #pragma unroll
    for (int i = 0; i < 8; i++) {
        size_t off = (size_t)(row0 + i) * M + col0;
        float v[8];
        #pragma unroll
        for (int j = 0; j < 8; j++) {
            float t = acc[i][j];
            if (EPI != 0) t += bias_r[j];
            v[j] = t;
        }
        if (EPI == 1) {
            #pragma unroll
            for (int j = 0; j < 8; j++) v[j] += res[off + j];
        }
        if (EPI == 2) {
            #pragma unroll
            for (int j = 0; j < 8; j++) v[j] = fmaxf(v[j], 0.0f);
        }
        *(float4*)&C[off]     = make_float4(v[0], v[1], v[2], v[3]);
        *(float4*)&C[off + 4] = make_float4(v[4], v[5], v[6], v[7]);
    }
}

// ---------------------------------------------------------------------------
// Causal flash attention, fp32. One CTA per (q-tile of 64, head, batch).
// 256 threads = 16x16, each owns a 4x4 microtile.
// qkv layout: row = b*T + t, cols: q at h*64, k at 384+h*64, v at 768+h*64.
// o layout:  [N, 384] with col = h*64 + d  (heads concatenated).
// ---------------------------------------------------------------------------
__global__ void __launch_bounds__(256) attn_kernel(const float* __restrict__ qkv,
                                                   float* __restrict__ o)
{
    extern __shared__ float smx[];
    float* Qs = smx;                 // [64][64]
    float* Kt = Qs + 64 * 64;        // [64 d][65]  (transposed, padded)
    float* Vs = Kt + 64 * 65;        // [64][64]
    float* Ps = Vs + 64 * 64;        // [64][64]

    const int qt = blockIdx.x;       // 0..3
    const int h  = blockIdx.y;       // 0..5
    const int b  = blockIdx.z;       // 0..127
    const int tid = threadIdx.x;
    const int tx = tid & 15, ty = tid >> 4;
    const int rb = ty * 4, cb = tx * 4;

    const size_t qrow0 = (size_t)(b * TT + qt * 64);

    // Load Q tile
    {
        const float* qg = qkv + qrow0 * QKVW + h * 64;
        for (int f = tid; f < 1024; f += 256) {
            int r = f >> 4, c4 = (f & 15) << 2;
            *(float4*)&Qs[r * 64 + c4] = *(const float4*)(qg + (size_t)r * QKVW + c4);
        }
    }

    float m[4], l[4], acc[4][4];
    #pragma unroll
    for (int i = 0; i < 4; i++) {
        m[i] = -1e30f; l[i] = 0.0f;
        #pragma unroll
        for (int j = 0; j < 4; j++) acc[i][j] = 0.0f;
    }

    for (int jt = 0; jt <= qt; jt++) {
        __syncthreads();   // prior PV reads of Vs/Ps done; Q load visible on first iter
        // Load K (transposed) and V
        {
            const float* kg = qkv + (size_t)(b * TT + jt * 64) * QKVW + CC + h * 64;
            const float* vg = kg + CC;
            for (int f = tid; f < 1024; f += 256) {
                int r = f >> 4, c4 = (f & 15) << 2;
                float4 kv = *(const float4*)(kg + (size_t)r * QKVW + c4);
                Kt[(c4 + 0) * 65 + r] = kv.x;
                Kt[(c4 + 1) * 65 + r] = kv.y;
                Kt[(c4 + 2) * 65 + r] = kv.z;
                Kt[(c4 + 3) * 65 + r] = kv.w;
                *(float4*)&Vs[r * 64 + c4] = *(const float4*)(vg + (size_t)r * QKVW + c4);
            }
        }
        __syncthreads();

        // S = Q K^T  (4x4 per thread)
        float s[4][4];
        #pragma unroll
        for (int i = 0; i < 4; i++)
            #pragma unroll
            for (int j = 0; j < 4; j++) s[i][j] = 0.0f;

        #pragma unroll 8
        for (int d = 0; d < 64; d++) {
            float qv[4], kv[4];
            #pragma unroll
            for (int i = 0; i < 4; i++) qv[i] = Qs[(rb + i) * 64 + d];
            #pragma unroll
            for (int j = 0; j < 4; j++) kv[j] = Kt[d * 65 + cb + j];
            #pragma unroll
            for (int i = 0; i < 4; i++)
                #pragma unroll
                for (int j = 0; j < 4; j++)
                    s[i][j] = fmaf(qv[i], kv[j], s[i][j]);
        }

        // scale + causal mask (only the diagonal tile needs masking)
        if (jt == qt) {
            #pragma unroll
            for (int i = 0; i < 4; i++)
                #pragma unroll
                for (int j = 0; j < 4; j++)
                    s[i][j] = (cb + j > rb + i) ? -1e30f : s[i][j] * ATT_SCALE;
        } else {
            #pragma unroll
            for (int i = 0; i < 4; i++)
                #pragma unroll
                for (int j = 0; j < 4; j++)
                    s[i][j] *= ATT_SCALE;
        }

        // online softmax (row reduction across the 16 tx lanes)
        #pragma unroll
        for (int i = 0; i < 4; i++) {
            float tmax = fmaxf(fmaxf(s[i][0], s[i][1]), fmaxf(s[i][2], s[i][3]));
            #pragma unroll
            for (int off = 8; off > 0; off >>= 1)
                tmax = fmaxf(tmax, __shfl_xor_sync(0xffffffffu, tmax, off));
            float mn  = fmaxf(m[i], tmax);
            float fac = __expf(m[i] - mn);
            float ps = 0.0f;
            #pragma unroll
            for (int j = 0; j < 4; j++) {
                float p = __expf(s[i][j] - mn);
                s[i][j] = p;
                ps += p;
            }
            #pragma unroll
            for (int off = 8; off > 0; off >>= 1)
                ps += __shfl_xor_sync(0xffffffffu, ps, off);
            l[i] = l[i] * fac + ps;
            #pragma unroll
            for (int j = 0; j < 4; j++) acc[i][j] *= fac;
            m[i] = mn;
        }

        // stage P
        #pragma unroll
        for (int i = 0; i < 4; i++)
            *(float4*)&Ps[(rb + i) * 64 + cb] =
                make_float4(s[i][0], s[i][1], s[i][2], s[i][3]);
        __syncthreads();

        // O += P V
        #pragma unroll 4
        for (int j = 0; j < 64; j++) {
            float4 v = *(const float4*)&Vs[j * 64 + cb];
            #pragma unroll
            for (int i = 0; i < 4; i++) {
                float p = Ps[(rb + i) * 64 + j];
                acc[i][0] = fmaf(p, v.x, acc[i][0]);
                acc[i][1] = fmaf(p, v.y, acc[i][1]);
                acc[i][2] = fmaf(p, v.z, acc[i][2]);
                acc[i][3] = fmaf(p, v.w, acc[i][3]);
            }
        }
    }

    // normalize + write (concat-heads layout)
    #pragma unroll
    for (int i = 0; i < 4; i++) {
        float inv = 1.0f / l[i];
        float4 ov = make_float4(acc[i][0] * inv, acc[i][1] * inv,
                                acc[i][2] * inv, acc[i][3] * inv);
        *(float4*)&o[(qrow0 + rb + i) * CC + h * 64 + cb] = ov;
    }
}

// ---------------------------------------------------------------------------
// Launch
// ---------------------------------------------------------------------------
extern "C" void kernel_launch(void* const* d_in, const int* in_sizes, int n_in,
                              void* d_out, int out_size)
{
    const float* x   = (const float*)d_in[0];
    const float* Wq  = (const float*)d_in[1];
    const float* Wk  = (const float*)d_in[2];
    const float* Wv  = (const float*)d_in[3];
    const float* Wo  = (const float*)d_in[4];
    const float* bo  = (const float*)d_in[5];
    const float* W1  = (const float*)d_in[6];
    const float* b1  = (const float*)d_in[7];
    const float* W2  = (const float*)d_in[8];
    const float* b2  = (const float*)d_in[9];
    const float* g1  = (const float*)d_in[10];
    const float* be1 = (const float*)d_in[11];
    const float* g2  = (const float*)d_in[12];
    const float* be2 = (const float*)d_in[13];
    float* out = (float*)d_out;

    float *xn, *qkv, *o, *x1, *xn2, *hb, *wqkv;
    cudaGetSymbolAddress((void**)&xn,   g_xn);
    cudaGetSymbolAddress((void**)&qkv,  g_qkv);
    cudaGetSymbolAddress((void**)&o,    g_o);
    cudaGetSymbolAddress((void**)&x1,   g_x1);
    cudaGetSymbolAddress((void**)&xn2,  g_xn2);
    cudaGetSymbolAddress((void**)&hb,   g_h);
    cudaGetSymbolAddress((void**)&wqkv, g_wqkv);

    // 1. pack QKV weights
    pack_w_kernel<<<(CC * QKVW + 255) / 256, 256>>>(Wq, Wk, Wv, wqkv);

    // 2. LN1
    ln_kernel<<<NROWS, 128>>>(x, g1, be1, xn);

    // 3. QKV projection
    sgemm_kernel<0><<<dim3(QKVW / 128, NROWS / 128), 256>>>(
        xn, wqkv, qkv, NROWS, CC, QKVW, nullptr, nullptr);

    // 4. causal attention
    cudaFuncSetAttribute(attn_kernel,
                         cudaFuncAttributeMaxDynamicSharedMemorySize, 65792);
    attn_kernel<<<dim3(4, HH, BB), 256, 65792>>>(qkv, o);

    // 5. output projection + bias + residual
    sgemm_kernel<1><<<dim3(CC / 128, NROWS / 128), 256>>>(
        o, Wo, x1, NROWS, CC, CC, bo, x);

    // 6. LN2
    ln_kernel<<<NROWS, 128>>>(x1, g2, be2, xn2);

    // 7. MLP up + ReLU
    sgemm_kernel<2><<<dim3(FFN / 128, NROWS / 128), 256>>>(
        xn2, W1, hb, NROWS, CC, FFN, b1, nullptr);

    // 8. MLP down + bias + residual -> out
    sgemm_kernel<1><<<dim3(CC / 128, NROWS / 128), 256>>>(
        hb, W2, out, NROWS, FFN, CC, b2, x1);
}

// round 3
// speedup vs baseline: 1.9329x; 1.9329x over previous
#include <cuda_runtime.h>
#include <cuda_bf16.h>
#include <math.h>
#include <stdint.h>

// Problem constants
#define BB   128
#define TT   256
#define CC   384
#define HH   6
#define DD   64
#define NROWS (BB*TT)          // 32768
#define QKVW  (3*CC)           // 1152
#define FFN   (4*CC)           // 1536
#define LN_EPS 1e-5f
#define ATT_SCALE 0.05103103630798287f   // 384^-0.5

typedef __nv_bfloat16 bf16;

// ---------------------------------------------------------------------------
// Scratch (device globals; allocation is forbidden)
// ---------------------------------------------------------------------------
__device__ bf16  g_xnh [(size_t)NROWS*CC];
__device__ bf16  g_xnl [(size_t)NROWS*CC];
__device__ float g_qkv [(size_t)NROWS*QKVW];
__device__ bf16  g_oh  [(size_t)NROWS*CC];
__device__ bf16  g_ol  [(size_t)NROWS*CC];
__device__ float g_x1  [(size_t)NROWS*CC];
__device__ bf16  g_xn2h[(size_t)NROWS*CC];
__device__ bf16  g_xn2l[(size_t)NROWS*CC];
__device__ bf16  g_hh  [(size_t)NROWS*FFN];
__device__ bf16  g_hl  [(size_t)NROWS*FFN];
// packed weights, [N, K] K-major bf16 hi/lo
__device__ bf16  g_bqkvh[(size_t)QKVW*CC];
__device__ bf16  g_bqkvl[(size_t)QKVW*CC];
__device__ bf16  g_boh  [(size_t)CC*CC];
__device__ bf16  g_bol  [(size_t)CC*CC];
__device__ bf16  g_b1h  [(size_t)FFN*CC];
__device__ bf16  g_b1l  [(size_t)FFN*CC];
__device__ bf16  g_b2h  [(size_t)CC*FFN];
__device__ bf16  g_b2l  [(size_t)CC*FFN];

// ---------------------------------------------------------------------------
// Helpers
// ---------------------------------------------------------------------------
__device__ __forceinline__ uint32_t smem_u32(const void* p) {
    return (uint32_t)__cvta_generic_to_shared(p);
}

__device__ __forceinline__ void split_bf16(float v, bf16& h, bf16& l) {
    h = __float2bfloat16(v);
    l = __float2bfloat16(v - __bfloat162float(h));
}

#define CP_ASYNC16(dst, src) \
    asm volatile("cp.async.cg.shared.global [%0], [%1], 16;" :: "r"(dst), "l"(src))
#define CP_COMMIT() asm volatile("cp.async.commit_group;" ::: "memory")
#define CP_WAIT(n)  asm volatile("cp.async.wait_group %0;" :: "n"(n) : "memory")

#define LDSM_X4(r0, r1, r2, r3, addr) \
    asm volatile("ldmatrix.sync.aligned.m8n8.x4.shared.b16 {%0,%1,%2,%3}, [%4];" \
        : "=r"(r0), "=r"(r1), "=r"(r2), "=r"(r3) : "r"(addr))

#define MMA_BF16(d0, d1, d2, d3, a0, a1, a2, a3, b0, b1) \
    asm volatile("mma.sync.aligned.m16n8k16.row.col.f32.bf16.bf16.f32 " \
        "{%0,%1,%2,%3}, {%4,%5,%6,%7}, {%8,%9}, {%0,%1,%2,%3};" \
        : "+f"(d0), "+f"(d1), "+f"(d2), "+f"(d3) \
        : "r"(a0), "r"(a1), "r"(a2), "r"(a3), "r"(b0), "r"(b1))

// ---------------------------------------------------------------------------
// Weight prep
// ---------------------------------------------------------------------------
__global__ void pack_wqkv_kernel(const float* __restrict__ Wq,
                                 const float* __restrict__ Wk,
                                 const float* __restrict__ Wv,
                                 bf16* __restrict__ oh, bf16* __restrict__ ol)
{
    int idx = blockIdx.x * 256 + threadIdx.x;
    if (idx >= QKVW * CC) return;
    int n = idx / CC, k = idx % CC;
    int proj = n / CC, hd = n % CC;
    int h = hd >> 6, d = hd & 63;
    const float* W = (proj == 0) ? Wq : ((proj == 1) ? Wk : Wv);
    float v = W[(size_t)(h * CC + k) * DD + d];
    split_bf16(v, oh[idx], ol[idx]);
}

// out[n*K+k] = W[k*N+n]
__global__ void transpose_split_kernel(const float* __restrict__ W,
                                       bf16* __restrict__ oh, bf16* __restrict__ ol,
                                       int N, int K)
{
    int idx = blockIdx.x * 256 + threadIdx.x;
    if (idx >= N * K) return;
    int n = idx / K, k = idx % K;
    split_bf16(W[(size_t)k * N + n], oh[idx], ol[idx]);
}

// ---------------------------------------------------------------------------
// LayerNorm with fused bf16 hi/lo split output
// ---------------------------------------------------------------------------
__global__ void __launch_bounds__(128) ln_split_kernel(const float* __restrict__ x,
                                                       const float* __restrict__ g,
                                                       const float* __restrict__ be,
                                                       bf16* __restrict__ oh,
                                                       bf16* __restrict__ ol)
{
    const int row = blockIdx.x;
    const int tid = threadIdx.x;
    const float* xr = x + (size_t)row * CC;

    float v0 = xr[tid], v1 = xr[tid + 128], v2 = xr[tid + 256];
    float s  = v0 + v1 + v2;
    float sq = v0*v0 + v1*v1 + v2*v2;

    #pragma unroll
    for (int off = 16; off > 0; off >>= 1) {
        s  += __shfl_xor_sync(0xffffffffu, s,  off);
        sq += __shfl_xor_sync(0xffffffffu, sq, off);
    }
    __shared__ float ss[4], ssq[4];
    const int wid = tid >> 5, lane = tid & 31;
    if (lane == 0) { ss[wid] = s; ssq[wid] = sq; }
    __syncthreads();
    s  = ss[0]  + ss[1]  + ss[2]  + ss[3];
    sq = ssq[0] + ssq[1] + ssq[2] + ssq[3];

    const float mu  = s * (1.0f / CC);
    const float var = sq * (1.0f / CC) - mu * mu;
    const float inv = rsqrtf(var + LN_EPS);

    size_t rb = (size_t)row * CC;
    float y0 = (v0 - mu) * inv * g[tid      ] + be[tid      ];
    float y1 = (v1 - mu) * inv * g[tid + 128] + be[tid + 128];
    float y2 = (v2 - mu) * inv * g[tid + 256] + be[tid + 256];
    split_bf16(y0, oh[rb + tid      ], ol[rb + tid      ]);
    split_bf16(y1, oh[rb + tid + 128], ol[rb + tid + 128]);
    split_bf16(y2, oh[rb + tid + 256], ol[rb + tid + 256]);
}

// ---------------------------------------------------------------------------
// HMMA bf16x3 GEMM.  C[N,M] = A[N,K] @ B[M,K]^T, A/B are hi/lo bf16 splits.
// CTA tile 128x128, 8 warps (2x4), warp tile 64x32, K-chunks of 32,
// cp.async double-buffered, smem rows padded to 80B (conflict-free ldmatrix).
//   EPI 0: f32 out   EPI 1: +bias+res -> f32   EPI 2: relu(+bias) -> bf16 hi/lo
// ---------------------------------------------------------------------------
#define RPAD 80                       // bytes per smem row (32 bf16 + 16B pad)
#define T_AH 0
#define T_AL (128*RPAD)
#define T_BH (2*128*RPAD)
#define T_BL (3*128*RPAD)
#define BUFSZ (4*128*RPAD)            // 40960
#define SMG_TOTAL (2*BUFSZ)           // 81920

__device__ __forceinline__ void prefetch_chunk(
    uint32_t sbuf,
    const bf16* __restrict__ Ah, const bf16* __restrict__ Al,
    const bf16* __restrict__ Bh, const bf16* __restrict__ Bl,
    int row0, int col0, int K, int k0, int tid)
{
    #pragma unroll
    for (int i = 0; i < 2; i++) {
        int idx = tid + i * 256;               // 0..511
        int r = idx >> 2, cp = idx & 3;
        uint32_t doff = (uint32_t)(r * RPAD + cp * 16);
        size_t goffA = (size_t)(row0 + r) * K + k0 + cp * 8;
        size_t goffB = (size_t)(col0 + r) * K + k0 + cp * 8;
        CP_ASYNC16(sbuf + T_AH + doff, Ah + goffA);
        CP_ASYNC16(sbuf + T_AL + doff, Al + goffA);
        CP_ASYNC16(sbuf + T_BH + doff, Bh + goffB);
        CP_ASYNC16(sbuf + T_BL + doff, Bl + goffB);
    }
}

template <int EPI>
__global__ void __launch_bounds__(256)
mma_gemm_kernel(const bf16* __restrict__ Ah, const bf16* __restrict__ Al,
                const bf16* __restrict__ Bh, const bf16* __restrict__ Bl,
                float* __restrict__ Cf, bf16* __restrict__ Ch, bf16* __restrict__ Cl,
                int K, int M,
                const float* __restrict__ bias, const float* __restrict__ res)
{
    extern __shared__ char sm[];
    const uint32_t sbase = smem_u32(sm);
    const int tid  = threadIdx.x;
    const int warp = tid >> 5, lane = tid & 31;
    const int wrow = warp >> 2, wcol = warp & 3;   // 2 x 4 warp grid
    const int row0 = blockIdx.y * 128;
    const int col0 = blockIdx.x * 128;

    const int quad = lane >> 3, il = lane & 7;
    // ldmatrix lane->address offsets (within a tile, before kstep/mtile adds)
    const uint32_t aoff = (uint32_t)((wrow * 64 + (quad & 1) * 8 + il) * RPAD
                                     + (quad >> 1) * 16);
    const uint32_t boff = (uint32_t)((wcol * 32 + (quad >> 1) * 8 + il) * RPAD
                                     + (quad & 1) * 16);

    float acc[4][4][4];
    #pragma unroll
    for (int m = 0; m < 4; m++)
        #pragma unroll
        for (int n = 0; n < 4; n++)
            #pragma unroll
            for (int k = 0; k < 4; k++) acc[m][n][k] = 0.0f;

    const int nch = K >> 5;
    prefetch_chunk(sbase, Ah, Al, Bh, Bl, row0, col0, K, 0, tid);
    CP_COMMIT();

    for (int ch = 0; ch < nch; ch++) {
        if (ch + 1 < nch) {
            prefetch_chunk(sbase + ((ch + 1) & 1) * BUFSZ, Ah, Al, Bh, Bl,
                           row0, col0, K, (ch + 1) << 5, tid);
            CP_COMMIT();
            CP_WAIT(1);
        } else {
            CP_WAIT(0);
        }
        __syncthreads();

        const uint32_t sbuf = sbase + (ch & 1) * BUFSZ;
        #pragma unroll
        for (int ks = 0; ks < 2; ks++) {
            const uint32_t ksb = ks * 32;
            uint32_t bh[8], bl[8];
            LDSM_X4(bh[0], bh[1], bh[2], bh[3], sbuf + T_BH + boff + ksb);
            LDSM_X4(bh[4], bh[5], bh[6], bh[7], sbuf + T_BH + boff + ksb + 16 * RPAD);
            LDSM_X4(bl[0], bl[1], bl[2], bl[3], sbuf + T_BL + boff + ksb);
            LDSM_X4(bl[4], bl[5], bl[6], bl[7], sbuf + T_BL + boff + ksb + 16 * RPAD);

            #pragma unroll
            for (int mt = 0; mt < 4; mt++) {
                const uint32_t moff = mt * 16 * RPAD + ksb;
                uint32_t ah[4], al[4];
                LDSM_X4(ah[0], ah[1], ah[2], ah[3], sbuf + T_AH + aoff + moff);
                LDSM_X4(al[0], al[1], al[2], al[3], sbuf + T_AL + aoff + moff);
                #pragma unroll
                for (int nt = 0; nt < 4; nt++) {
                    float* d = acc[mt][nt];
                    MMA_BF16(d[0], d[1], d[2], d[3],
                             ah[0], ah[1], ah[2], ah[3], bh[nt*2], bh[nt*2+1]);
                    MMA_BF16(d[0], d[1], d[2], d[3],
                             al[0], al[1], al[2], al[3], bh[nt*2], bh[nt*2+1]);
                    MMA_BF16(d[0], d[1], d[2], d[3],
                             ah[0], ah[1], ah[2], ah[3], bl[nt*2], bl[nt*2+1]);
                }
            }
        }
        __syncthreads();
    }

    // Epilogue straight from registers
    const int r_l = lane >> 2;
    const int c_l = (lane & 3) << 1;
    #pragma unroll
    for (int mt = 0; mt < 4; mt++) {
        #pragma unroll
        for (int nt = 0; nt < 4; nt++) {
            const int r = row0 + wrow * 64 + mt * 16 + r_l;
            const int c = col0 + wcol * 32 + nt * 8 + c_l;
            const float* d = acc[mt][nt];
            #pragma unroll
            for (int half = 0; half < 2; half++) {
                const int rr = r + half * 8;
                const size_t off = (size_t)rr * M + c;
                float v0 = d[half * 2], v1 = d[half * 2 + 1];
                if (EPI == 0) {
                    *(float2*)&Cf[off] = make_float2(v0, v1);
                } else if (EPI == 1) {
                    float2 rv = *(const float2*)&res[off];
                    *(float2*)&Cf[off] = make_float2(v0 + bias[c] + rv.x,
                                                     v1 + bias[c + 1] + rv.y);
                } else {
                    v0 = fmaxf(v0 + bias[c],     0.0f);
                    v1 = fmaxf(v1 + bias[c + 1], 0.0f);
                    bf16 h0, l0, h1, l1;
                    split_bf16(v0, h0, l0);
                    split_bf16(v1, h1, l1);
                    __nv_bfloat162 ph, pl;
                    ph.x = h0; ph.y = h1;
                    pl.x = l0; pl.y = l1;
                    *(__nv_bfloat162*)&Ch[off] = ph;
                    *(__nv_bfloat162*)&Cl[off] = pl;
                }
            }
        }
    }
}

// ---------------------------------------------------------------------------
// Causal flash attention, fp32, writes o as bf16 hi/lo
// ---------------------------------------------------------------------------
__global__ void __launch_bounds__(256) attn_kernel(const float* __restrict__ qkv,
                                                   bf16* __restrict__ oh,
                                                   bf16* __restrict__ ol)
{
    extern __shared__ float smx[];
    float* Qs = smx;                 // [64][64]
    float* Kt = Qs + 64 * 64;        // [64 d][65]
    float* Vs = Kt + 64 * 65;        // [64][64]
    float* Ps = Vs + 64 * 64;        // [64][64]

    const int qt = blockIdx.x;
    const int h  = blockIdx.y;
    const int b  = blockIdx.z;
    const int tid = threadIdx.x;
    const int tx = tid & 15, ty = tid >> 4;
    const int rb = ty * 4, cb = tx * 4;

    const size_t qrow0 = (size_t)(b * TT + qt * 64);

    {
        const float* qg = qkv + qrow0 * QKVW + h * 64;
        for (int f = tid; f < 1024; f += 256) {
            int r = f >> 4, c4 = (f & 15) << 2;
            *(float4*)&Qs[r * 64 + c4] = *(const float4*)(qg + (size_t)r * QKVW + c4);
        }
    }

    float m[4], l[4], acc[4][4];
    #pragma unroll
    for (int i = 0; i < 4; i++) {
        m[i] = -1e30f; l[i] = 0.0f;
        #pragma unroll
        for (int j = 0; j < 4; j++) acc[i][j] = 0.0f;
    }

    for (int jt = 0; jt <= qt; jt++) {
        __syncthreads();
        {
            const float* kg = qkv + (size_t)(b * TT + jt * 64) * QKVW + CC + h * 64;
            const float* vg = kg + CC;
            for (int f = tid; f < 1024; f += 256) {
                int r = f >> 4, c4 = (f & 15) << 2;
                float4 kv = *(const float4*)(kg + (size_t)r * QKVW + c4);
                Kt[(c4 + 0) * 65 + r] = kv.x;
                Kt[(c4 + 1) * 65 + r] = kv.y;
                Kt[(c4 + 2) * 65 + r] = kv.z;
                Kt[(c4 + 3) * 65 + r] = kv.w;
                *(float4*)&Vs[r * 64 + c4] = *(const float4*)(vg + (size_t)r * QKVW + c4);
            }
        }
        __syncthreads();

        float s[4][4];
        #pragma unroll
        for (int i = 0; i < 4; i++)
            #pragma unroll
            for (int j = 0; j < 4; j++) s[i][j] = 0.0f;

        #pragma unroll 8
        for (int d = 0; d < 64; d++) {
            float qv[4], kv[4];
            #pragma unroll
            for (int i = 0; i < 4; i++) qv[i] = Qs[(rb + i) * 64 + d];
            #pragma unroll
            for (int j = 0; j < 4; j++) kv[j] = Kt[d * 65 + cb + j];
            #pragma unroll
            for (int i = 0; i < 4; i++)
                #pragma unroll
                for (int j = 0; j < 4; j++)
                    s[i][j] = fmaf(qv[i], kv[j], s[i][j]);
        }

        if (jt == qt) {
            #pragma unroll
            for (int i = 0; i < 4; i++)
                #pragma unroll
                for (int j = 0; j < 4; j++)
                    s[i][j] = (cb + j > rb + i) ? -1e30f : s[i][j] * ATT_SCALE;
        } else {
            #pragma unroll
            for (int i = 0; i < 4; i++)
                #pragma unroll
                for (int j = 0; j < 4; j++)
                    s[i][j] *= ATT_SCALE;
        }

        #pragma unroll
        for (int i = 0; i < 4; i++) {
            float tmax = fmaxf(fmaxf(s[i][0], s[i][1]), fmaxf(s[i][2], s[i][3]));
            #pragma unroll
            for (int off = 8; off > 0; off >>= 1)
                tmax = fmaxf(tmax, __shfl_xor_sync(0xffffffffu, tmax, off));
            float mn  = fmaxf(m[i], tmax);
            float fac = __expf(m[i] - mn);
            float ps = 0.0f;
            #pragma unroll
            for (int j = 0; j < 4; j++) {
                float p = __expf(s[i][j] - mn);
                s[i][j] = p;
                ps += p;
            }
            #pragma unroll
            for (int off = 8; off > 0; off >>= 1)
                ps += __shfl_xor_sync(0xffffffffu, ps, off);
            l[i] = l[i] * fac + ps;
            #pragma unroll
            for (int j = 0; j < 4; j++) acc[i][j] *= fac;
            m[i] = mn;
        }

        #pragma unroll
        for (int i = 0; i < 4; i++)
            *(float4*)&Ps[(rb + i) * 64 + cb] =
                make_float4(s[i][0], s[i][1], s[i][2], s[i][3]);
        __syncthreads();

        #pragma unroll 4
        for (int j = 0; j < 64; j++) {
            float4 v = *(const float4*)&Vs[j * 64 + cb];
            #pragma unroll
            for (int i = 0; i < 4; i++) {
                float p = Ps[(rb + i) * 64 + j];
                acc[i][0] = fmaf(p, v.x, acc[i][0]);
                acc[i][1] = fmaf(p, v.y, acc[i][1]);
                acc[i][2] = fmaf(p, v.z, acc[i][2]);
                acc[i][3] = fmaf(p, v.w, acc[i][3]);
            }
        }
    }

    #pragma unroll
    for (int i = 0; i < 4; i++) {
        float inv = 1.0f / l[i];
        size_t base = (qrow0 + rb + i) * CC + h * 64 + cb;
        #pragma unroll
        for (int j = 0; j < 4; j += 2) {
            bf16 h0, l0, h1, l1;
            split_bf16(acc[i][j]     * inv, h0, l0);
            split_bf16(acc[i][j + 1] * inv, h1, l1);
            __nv_bfloat162 ph, pl;
            ph.x = h0; ph.y = h1;
            pl.x = l0; pl.y = l1;
            *(__nv_bfloat162*)&oh[base + j] = ph;
            *(__nv_bfloat162*)&ol[base + j] = pl;
        }
    }
}

// ---------------------------------------------------------------------------
// Launch
// ---------------------------------------------------------------------------
extern "C" void kernel_launch(void* const* d_in, const int* in_sizes, int n_in,
                              void* d_out, int out_size)
{
    const float* x   = (const float*)d_in[0];
    const float* Wq  = (const float*)d_in[1];
    const float* Wk  = (const float*)d_in[2];
    const float* Wv  = (const float*)d_in[3];
    const float* Wo  = (const float*)d_in[4];
    const float* bo  = (const float*)d_in[5];
    const float* W1  = (const float*)d_in[6];
    const float* b1  = (const float*)d_in[7];
    const float* W2  = (const float*)d_in[8];
    const float* b2  = (const float*)d_in[9];
    const float* g1  = (const float*)d_in[10];
    const float* be1 = (const float*)d_in[11];
    const float* g2  = (const float*)d_in[12];
    const float* be2 = (const float*)d_in[13];
    float* out = (float*)d_out;

    bf16 *xnh, *xnl, *ohp, *olp, *xn2h, *xn2l, *hh, *hl;
    bf16 *bqkvh, *bqkvl, *boh, *bol, *b1h, *b1l, *b2h, *b2l;
    float *qkv, *x1;
    cudaGetSymbolAddress((void**)&xnh,   g_xnh);
    cudaGetSymbolAddress((void**)&xnl,   g_xnl);
    cudaGetSymbolAddress((void**)&qkv,   g_qkv);
    cudaGetSymbolAddress((void**)&ohp,   g_oh);
    cudaGetSymbolAddress((void**)&olp,   g_ol);
    cudaGetSymbolAddress((void**)&x1,    g_x1);
    cudaGetSymbolAddress((void**)&xn2h,  g_xn2h);
    cudaGetSymbolAddress((void**)&xn2l,  g_xn2l);
    cudaGetSymbolAddress((void**)&hh,    g_hh);
    cudaGetSymbolAddress((void**)&hl,    g_hl);
    cudaGetSymbolAddress((void**)&bqkvh, g_bqkvh);
    cudaGetSymbolAddress((void**)&bqkvl, g_bqkvl);
    cudaGetSymbolAddress((void**)&boh,   g_boh);
    cudaGetSymbolAddress((void**)&bol,   g_bol);
    cudaGetSymbolAddress((void**)&b1h,   g_b1h);
    cudaGetSymbolAddress((void**)&b1l,   g_b1l);
    cudaGetSymbolAddress((void**)&b2h,   g_b2h);
    cudaGetSymbolAddress((void**)&b2l,   g_b2l);

    cudaFuncSetAttribute(mma_gemm_kernel<0>,
                         cudaFuncAttributeMaxDynamicSharedMemorySize, SMG_TOTAL);
    cudaFuncSetAttribute(mma_gemm_kernel<1>,
                         cudaFuncAttributeMaxDynamicSharedMemorySize, SMG_TOTAL);
    cudaFuncSetAttribute(mma_gemm_kernel<2>,
                         cudaFuncAttributeMaxDynamicSharedMemorySize, SMG_TOTAL);
    cudaFuncSetAttribute(attn_kernel,
                         cudaFuncAttributeMaxDynamicSharedMemorySize, 65792);

    // weight prep
    pack_wqkv_kernel<<<(QKVW * CC + 255) / 256, 256>>>(Wq, Wk, Wv, bqkvh, bqkvl);
    transpose_split_kernel<<<(CC * CC + 255) / 256, 256>>>(Wo, boh, bol, CC, CC);
    transpose_split_kernel<<<(FFN * CC + 255) / 256, 256>>>(W1, b1h, b1l, FFN, CC);
    transpose_split_kernel<<<(CC * FFN + 255) / 256, 256>>>(W2, b2h, b2l, CC, FFN);

    // LN1 (fused split)
    ln_split_kernel<<<NROWS, 128>>>(x, g1, be1, xnh, xnl);

    // QKV projection
    mma_gemm_kernel<0><<<dim3(QKVW / 128, NROWS / 128), 256, SMG_TOTAL>>>(
        xnh, xnl, bqkvh, bqkvl, qkv, nullptr, nullptr, CC, QKVW, nullptr, nullptr);

    // causal attention (writes o hi/lo)
    attn_kernel<<<dim3(4, HH, BB), 256, 65792>>>(qkv, ohp, olp);

    // output projection + bias + residual
    mma_gemm_kernel<1><<<dim3(CC / 128, NROWS / 128), 256, SMG_TOTAL>>>(
        ohp, olp, boh, bol, x1, nullptr, nullptr, CC, CC, bo, x);

    // LN2 (fused split)
    ln_split_kernel<<<NROWS, 128>>>(x1, g2, be2, xn2h, xn2l);

    // MLP up + ReLU (writes h hi/lo)
    mma_gemm_kernel<2><<<dim3(FFN / 128, NROWS / 128), 256, SMG_TOTAL>>>(
        xn2h, xn2l, b1h, b1l, nullptr, hh, hl, CC, FFN, b1, nullptr);

    // MLP down + bias + residual -> out
    mma_gemm_kernel<1><<<dim3(CC / 128, NROWS / 128), 256, SMG_TOTAL>>>(
        hh, hl, b2h, b2l, out, nullptr, nullptr, FFN, CC, b2, x1);
}

// round 4
// speedup vs baseline: 4.2517x; 2.1997x over previous
#include <cuda_runtime.h>
#include <cuda_fp16.h>
#include <math.h>
#include <stdint.h>

// Problem constants
#define BB   128
#define TT   256
#define CC   384
#define HH   6
#define DD   64
#define NROWS (BB*TT)          // 32768
#define QKVW  (3*CC)           // 1152
#define FFN   (4*CC)           // 1536
#define LN_EPS 1e-5f
#define ATT_SCALE 0.05103103630798287f   // 384^-0.5

typedef __half half_t;

// ---------------------------------------------------------------------------
// Scratch (device globals; allocation is forbidden)
// ---------------------------------------------------------------------------
__device__ half_t g_xn  [(size_t)NROWS*CC];
__device__ half_t g_qkv [(size_t)NROWS*QKVW];
__device__ half_t g_o   [(size_t)NROWS*CC];
__device__ float  g_x1  [(size_t)NROWS*CC];
__device__ half_t g_xn2 [(size_t)NROWS*CC];
__device__ half_t g_h   [(size_t)NROWS*FFN];
// packed weights, [N, K] K-major fp16
__device__ half_t g_wqkv[(size_t)QKVW*CC];
__device__ half_t g_wo  [(size_t)CC*CC];
__device__ half_t g_w1  [(size_t)FFN*CC];
__device__ half_t g_w2  [(size_t)CC*FFN];

// ---------------------------------------------------------------------------
// Helpers
// ---------------------------------------------------------------------------
__device__ __forceinline__ uint32_t smem_u32(const void* p) {
    return (uint32_t)__cvta_generic_to_shared(p);
}

#define CP_ASYNC16(dst, src) \
    asm volatile("cp.async.cg.shared.global [%0], [%1], 16;" :: "r"(dst), "l"(src))
#define CP_COMMIT() asm volatile("cp.async.commit_group;" ::: "memory")
#define CP_WAIT(n)  asm volatile("cp.async.wait_group %0;" :: "n"(n) : "memory")

#define LDSM_X4(r0, r1, r2, r3, addr) \
    asm volatile("ldmatrix.sync.aligned.m8n8.x4.shared.b16 {%0,%1,%2,%3}, [%4];" \
        : "=r"(r0), "=r"(r1), "=r"(r2), "=r"(r3) : "r"(addr))

#define MMA_F16(d0, d1, d2, d3, a0, a1, a2, a3, b0, b1) \
    asm volatile("mma.sync.aligned.m16n8k16.row.col.f32.f16.f16.f32 " \
        "{%0,%1,%2,%3}, {%4,%5,%6,%7}, {%8,%9}, {%0,%1,%2,%3};" \
        : "+f"(d0), "+f"(d1), "+f"(d2), "+f"(d3) \
        : "r"(a0), "r"(a1), "r"(a2), "r"(a3), "r"(b0), "r"(b1))

// ---------------------------------------------------------------------------
// Weight prep
// ---------------------------------------------------------------------------
__global__ void pack_wqkv_kernel(const float* __restrict__ Wq,
                                 const float* __restrict__ Wk,
                                 const float* __restrict__ Wv,
                                 half_t* __restrict__ out)
{
    int idx = blockIdx.x * 256 + threadIdx.x;
    if (idx >= QKVW * CC) return;
    int n = idx / CC, k = idx % CC;
    int proj = n / CC, hd = n % CC;
    int h = hd >> 6, d = hd & 63;
    const float* W = (proj == 0) ? Wq : ((proj == 1) ? Wk : Wv);
    out[idx] = __float2half(W[(size_t)(h * CC + k) * DD + d]);
}

// out[n*K+k] = W[k*N+n]
__global__ void transpose_pack_kernel(const float* __restrict__ W,
                                      half_t* __restrict__ out, int N, int K)
{
    int idx = blockIdx.x * 256 + threadIdx.x;
    if (idx >= N * K) return;
    int n = idx / K, k = idx % K;
    out[idx] = __float2half(W[(size_t)k * N + n]);
}

// ---------------------------------------------------------------------------
// LayerNorm with fp16 output
// ---------------------------------------------------------------------------
__global__ void __launch_bounds__(128) ln_kernel(const float* __restrict__ x,
                                                 const float* __restrict__ g,
                                                 const float* __restrict__ be,
                                                 half_t* __restrict__ out)
{
    const int row = blockIdx.x;
    const int tid = threadIdx.x;
    const float* xr = x + (size_t)row * CC;

    float v0 = xr[tid], v1 = xr[tid + 128], v2 = xr[tid + 256];
    float s  = v0 + v1 + v2;
    float sq = v0*v0 + v1*v1 + v2*v2;

    #pragma unroll
    for (int off = 16; off > 0; off >>= 1) {
        s  += __shfl_xor_sync(0xffffffffu, s,  off);
        sq += __shfl_xor_sync(0xffffffffu, sq, off);
    }
    __shared__ float ss[4], ssq[4];
    const int wid = tid >> 5, lane = tid & 31;
    if (lane == 0) { ss[wid] = s; ssq[wid] = sq; }
    __syncthreads();
    s  = ss[0]  + ss[1]  + ss[2]  + ss[3];
    sq = ssq[0] + ssq[1] + ssq[2] + ssq[3];

    const float mu  = s * (1.0f / CC);
    const float var = sq * (1.0f / CC) - mu * mu;
    const float inv = rsqrtf(var + LN_EPS);

    size_t rb = (size_t)row * CC;
    out[rb + tid      ] = __float2half((v0 - mu) * inv * g[tid      ] + be[tid      ]);
    out[rb + tid + 128] = __float2half((v1 - mu) * inv * g[tid + 128] + be[tid + 128]);
    out[rb + tid + 256] = __float2half((v2 - mu) * inv * g[tid + 256] + be[tid + 256]);
}

// ---------------------------------------------------------------------------
// fp16 HMMA GEMM.  C[N,M] = A[N,K] @ B[M,K]^T.
// CTA tile 128x128, 8 warps (2x4), warp tile 64x32, K-chunks of 64,
// cp.async double-buffered, smem rows padded to 144B (conflict-free ldmatrix).
//   EPI 0: fp16 out   EPI 1: +bias+res -> f32   EPI 2: relu(+bias) -> fp16
// ---------------------------------------------------------------------------
#define RPAD 144                      // bytes per smem row (64 fp16 + 16B pad)
#define T_A  0
#define T_B  (128*RPAD)
#define BUFSZ (2*128*RPAD)            // 36864
#define SMG_TOTAL (2*BUFSZ)           // 73728

__device__ __forceinline__ void prefetch_chunk(
    uint32_t sbuf, const half_t* __restrict__ A, const half_t* __restrict__ B,
    int row0, int col0, int K, int k0, int tid)
{
    #pragma unroll
    for (int i = 0; i < 8; i++) {
        int idx = tid + i * 256;           // 0..2047
        int r = idx >> 3, cp = idx & 7;
        if (r < 128) {
            CP_ASYNC16(sbuf + T_A + (uint32_t)(r * RPAD + cp * 16),
                       A + (size_t)(row0 + r) * K + k0 + cp * 8);
        } else {
            int rr = r - 128;
            CP_ASYNC16(sbuf + T_B + (uint32_t)(rr * RPAD + cp * 16),
                       B + (size_t)(col0 + rr) * K + k0 + cp * 8);
        }
    }
}

template <int EPI>
__global__ void __launch_bounds__(256)
mma_gemm_kernel(const half_t* __restrict__ A, const half_t* __restrict__ B,
                float* __restrict__ Cf, half_t* __restrict__ Ch,
                int K, int M,
                const float* __restrict__ bias, const float* __restrict__ res)
{
    extern __shared__ char sm[];
    const uint32_t sbase = smem_u32(sm);
    const int tid  = threadIdx.x;
    const int warp = tid >> 5, lane = tid & 31;
    const int wrow = warp >> 2, wcol = warp & 3;   // 2 x 4 warp grid
    const int row0 = blockIdx.y * 128;
    const int col0 = blockIdx.x * 128;

    const int quad = lane >> 3, il = lane & 7;
    const uint32_t aoff = (uint32_t)((wrow * 64 + (quad & 1) * 8 + il) * RPAD
                                     + (quad >> 1) * 16);
    const uint32_t boff = (uint32_t)((wcol * 32 + (quad >> 1) * 8 + il) * RPAD
                                     + (quad & 1) * 16);

    float acc[4][4][4];
    #pragma unroll
    for (int m = 0; m < 4; m++)
        #pragma unroll
        for (int n = 0; n < 4; n++)
            #pragma unroll
            for (int k = 0; k < 4; k++) acc[m][n][k] = 0.0f;

    const int nch = K >> 6;
    prefetch_chunk(sbase, A, B, row0, col0, K, 0, tid);
    CP_COMMIT();

    for (int ch = 0; ch < nch; ch++) {
        if (ch + 1 < nch) {
            prefetch_chunk(sbase + ((ch + 1) & 1) * BUFSZ, A, B,
                           row0, col0, K, (ch + 1) << 6, tid);
            CP_COMMIT();
            CP_WAIT(1);
        } else {
            CP_WAIT(0);
        }
        __syncthreads();

        const uint32_t sbuf = sbase + (ch & 1) * BUFSZ;
        #pragma unroll
        for (int ks = 0; ks < 4; ks++) {
            const uint32_t ksb = ks * 32;          // 16 fp16 = 32B per kstep
            uint32_t b[8];
            LDSM_X4(b[0], b[1], b[2], b[3], sbuf + T_B + boff + ksb);
            LDSM_X4(b[4], b[5], b[6], b[7], sbuf + T_B + boff + ksb + 16 * RPAD);

            #pragma unroll
            for (int mt = 0; mt < 4; mt++) {
                uint32_t a[4];
                LDSM_X4(a[0], a[1], a[2], a[3],
                        sbuf + T_A + aoff + mt * 16 * RPAD + ksb);
                #pragma unroll
                for (int nt = 0; nt < 4; nt++) {
                    float* d = acc[mt][nt];
                    MMA_F16(d[0], d[1], d[2], d[3],
                            a[0], a[1], a[2], a[3], b[nt*2], b[nt*2+1]);
                }
            }
        }
        __syncthreads();
    }

    // Epilogue straight from registers
    const int r_l = lane >> 2;
    const int c_l = (lane & 3) << 1;
    #pragma unroll
    for (int mt = 0; mt < 4; mt++) {
        #pragma unroll
        for (int nt = 0; nt < 4; nt++) {
            const int r = row0 + wrow * 64 + mt * 16 + r_l;
            const int c = col0 + wcol * 32 + nt * 8 + c_l;
            const float* d = acc[mt][nt];
            #pragma unroll
            for (int half_i = 0; half_i < 2; half_i++) {
                const int rr = r + half_i * 8;
                const size_t off = (size_t)rr * M + c;
                float v0 = d[half_i * 2], v1 = d[half_i * 2 + 1];
                if (EPI == 0) {
                    *(__half2*)&Ch[off] = __floats2half2_rn(v0, v1);
                } else if (EPI == 1) {
                    float2 rv = *(const float2*)&res[off];
                    *(float2*)&Cf[off] = make_float2(v0 + bias[c] + rv.x,
                                                     v1 + bias[c + 1] + rv.y);
                } else {
                    v0 = fmaxf(v0 + bias[c],     0.0f);
                    v1 = fmaxf(v1 + bias[c + 1], 0.0f);
                    *(__half2*)&Ch[off] = __floats2half2_rn(v0, v1);
                }
            }
        }
    }
}

// ---------------------------------------------------------------------------
// Causal flash attention, fp32 math, fp16 in/out.
// One CTA per (q-tile of 64, head, batch); 256 threads = 16x16, 4x4 microtile.
// ---------------------------------------------------------------------------
__global__ void __launch_bounds__(256) attn_kernel(const half_t* __restrict__ qkv,
                                                   half_t* __restrict__ o)
{
    extern __shared__ float smx[];
    float* Qs = smx;                 // [64][64]
    float* Kt = Qs + 64 * 64;        // [64 d][65]
    float* Vs = Kt + 64 * 65;        // [64][64]
    float* Ps = Vs + 64 * 64;        // [64][64]

    const int qt = blockIdx.x;
    const int h  = blockIdx.y;
    const int b  = blockIdx.z;
    const int tid = threadIdx.x;
    const int tx = tid & 15, ty = tid >> 4;
    const int rb = ty * 4, cb = tx * 4;

    const size_t qrow0 = (size_t)(b * TT + qt * 64);

    {
        const half_t* qg = qkv + qrow0 * QKVW + h * 64;
        for (int f = tid; f < 512; f += 256) {
            int r = f >> 3, c8 = (f & 7) << 3;
            uint4 v = *(const uint4*)(qg + (size_t)r * QKVW + c8);
            const __half2* hp = (const __half2*)&v;
            #pragma unroll
            for (int j = 0; j < 4; j++) {
                float2 fv = __half22float2(hp[j]);
                Qs[r * 64 + c8 + 2*j]     = fv.x;
                Qs[r * 64 + c8 + 2*j + 1] = fv.y;
            }
        }
    }

    float m[4], l[4], acc[4][4];
    #pragma unroll
    for (int i = 0; i < 4; i++) {
        m[i] = -1e30f; l[i] = 0.0f;
        #pragma unroll
        for (int j = 0; j < 4; j++) acc[i][j] = 0.0f;
    }

    for (int jt = 0; jt <= qt; jt++) {
        __syncthreads();
        {
            const half_t* kg = qkv + (size_t)(b * TT + jt * 64) * QKVW + CC + h * 64;
            const half_t* vg = kg + CC;
            for (int f = tid; f < 512; f += 256) {
                int r = f >> 3, c8 = (f & 7) << 3;
                uint4 kvv = *(const uint4*)(kg + (size_t)r * QKVW + c8);
                const __half2* kp = (const __half2*)&kvv;
                #pragma unroll
                for (int j = 0; j < 4; j++) {
                    float2 fv = __half22float2(kp[j]);
                    Kt[(c8 + 2*j)     * 65 + r] = fv.x;
                    Kt[(c8 + 2*j + 1) * 65 + r] = fv.y;
                }
                uint4 vvv = *(const uint4*)(vg + (size_t)r * QKVW + c8);
                const __half2* vp = (const __half2*)&vvv;
                #pragma unroll
                for (int j = 0; j < 4; j++) {
                    float2 fv = __half22float2(vp[j]);
                    Vs[r * 64 + c8 + 2*j]     = fv.x;
                    Vs[r * 64 + c8 + 2*j + 1] = fv.y;
                }
            }
        }
        __syncthreads();

        float s[4][4];
        #pragma unroll
        for (int i = 0; i < 4; i++)
            #pragma unroll
            for (int j = 0; j < 4; j++) s[i][j] = 0.0f;

        #pragma unroll 8
        for (int d = 0; d < 64; d++) {
            float qv[4], kv[4];
            #pragma unroll
            for (int i = 0; i < 4; i++) qv[i] = Qs[(rb + i) * 64 + d];
            #pragma unroll
            for (int j = 0; j < 4; j++) kv[j] = Kt[d * 65 + cb + j];
            #pragma unroll
            for (int i = 0; i < 4; i++)
                #pragma unroll
                for (int j = 0; j < 4; j++)
                    s[i][j] = fmaf(qv[i], kv[j], s[i][j]);
        }

        if (jt == qt) {
            #pragma unroll
            for (int i = 0; i < 4; i++)
                #pragma unroll
                for (int j = 0; j < 4; j++)
                    s[i][j] = (cb + j > rb + i) ? -1e30f : s[i][j] * ATT_SCALE;
        } else {
            #pragma unroll
            for (int i = 0; i < 4; i++)
                #pragma unroll
                for (int j = 0; j < 4; j++)
                    s[i][j] *= ATT_SCALE;
        }

        #pragma unroll
        for (int i = 0; i < 4; i++) {
            float tmax = fmaxf(fmaxf(s[i][0], s[i][1]), fmaxf(s[i][2], s[i][3]));
            #pragma unroll
            for (int off = 8; off > 0; off >>= 1)
                tmax = fmaxf(tmax, __shfl_xor_sync(0xffffffffu, tmax, off));
            float mn  = fmaxf(m[i], tmax);
            float fac = __expf(m[i] - mn);
            float ps = 0.0f;
            #pragma unroll
            for (int j = 0; j < 4; j++) {
                float p = __expf(s[i][j] - mn);
                s[i][j] = p;
                ps += p;
            }
            #pragma unroll
            for (int off = 8; off > 0; off >>= 1)
                ps += __shfl_xor_sync(0xffffffffu, ps, off);
            l[i] = l[i] * fac + ps;
            #pragma unroll
            for (int j = 0; j < 4; j++) acc[i][j] *= fac;
            m[i] = mn;
        }

        #pragma unroll
        for (int i = 0; i < 4; i++)
            *(float4*)&Ps[(rb + i) * 64 + cb] =
                make_float4(s[i][0], s[i][1], s[i][2], s[i][3]);
        __syncthreads();

        #pragma unroll 4
        for (int j = 0; j < 64; j++) {
            float4 v = *(const float4*)&Vs[j * 64 + cb];
            #pragma unroll
            for (int i = 0; i < 4; i++) {
                float p = Ps[(rb + i) * 64 + j];
                acc[i][0] = fmaf(p, v.x, acc[i][0]);
                acc[i][1] = fmaf(p, v.y, acc[i][1]);
                acc[i][2] = fmaf(p, v.z, acc[i][2]);
                acc[i][3] = fmaf(p, v.w, acc[i][3]);
            }
        }
    }

    #pragma unroll
    for (int i = 0; i < 4; i++) {
        float inv = 1.0f / l[i];
        size_t base = (qrow0 + rb + i) * CC + h * 64 + cb;
        *(__half2*)&o[base]     = __floats2half2_rn(acc[i][0] * inv, acc[i][1] * inv);
        *(__half2*)&o[base + 2] = __floats2half2_rn(acc[i][2] * inv, acc[i][3] * inv);
    }
}

// ---------------------------------------------------------------------------
// Launch
// ---------------------------------------------------------------------------
extern "C" void kernel_launch(void* const* d_in, const int* in_sizes, int n_in,
                              void* d_out, int out_size)
{
    const float* x   = (const float*)d_in[0];
    const float* Wq  = (const float*)d_in[1];
    const float* Wk  = (const float*)d_in[2];
    const float* Wv  = (const float*)d_in[3];
    const float* Wo  = (const float*)d_in[4];
    const float* bo  = (const float*)d_in[5];
    const float* W1  = (const float*)d_in[6];
    const float* b1  = (const float*)d_in[7];
    const float* W2  = (const float*)d_in[8];
    const float* b2  = (const float*)d_in[9];
    const float* g1  = (const float*)d_in[10];
    const float* be1 = (const float*)d_in[11];
    const float* g2  = (const float*)d_in[12];
    const float* be2 = (const float*)d_in[13];
    float* out = (float*)d_out;

    half_t *xn, *qkv, *o, *xn2, *hb, *wqkv, *wo, *w1, *w2;
    float *x1;
    cudaGetSymbolAddress((void**)&xn,   g_xn);
    cudaGetSymbolAddress((void**)&qkv,  g_qkv);
    cudaGetSymbolAddress((void**)&o,    g_o);
    cudaGetSymbolAddress((void**)&x1,   g_x1);
    cudaGetSymbolAddress((void**)&xn2,  g_xn2);
    cudaGetSymbolAddress((void**)&hb,   g_h);
    cudaGetSymbolAddress((void**)&wqkv, g_wqkv);
    cudaGetSymbolAddress((void**)&wo,   g_wo);
    cudaGetSymbolAddress((void**)&w1,   g_w1);
    cudaGetSymbolAddress((void**)&w2,   g_w2);

    cudaFuncSetAttribute(mma_gemm_kernel<0>,
                         cudaFuncAttributeMaxDynamicSharedMemorySize, SMG_TOTAL);
    cudaFuncSetAttribute(mma_gemm_kernel<1>,
                         cudaFuncAttributeMaxDynamicSharedMemorySize, SMG_TOTAL);
    cudaFuncSetAttribute(mma_gemm_kernel<2>,
                         cudaFuncAttributeMaxDynamicSharedMemorySize, SMG_TOTAL);
    cudaFuncSetAttribute(attn_kernel,
                         cudaFuncAttributeMaxDynamicSharedMemorySize, 65792);

    // weight prep
    pack_wqkv_kernel<<<(QKVW * CC + 255) / 256, 256>>>(Wq, Wk, Wv, wqkv);
    transpose_pack_kernel<<<(CC * CC + 255) / 256, 256>>>(Wo, wo, CC, CC);
    transpose_pack_kernel<<<(FFN * CC + 255) / 256, 256>>>(W1, w1, FFN, CC);
    transpose_pack_kernel<<<(CC * FFN + 255) / 256, 256>>>(W2, w2, CC, FFN);

    // LN1
    ln_kernel<<<NROWS, 128>>>(x, g1, be1, xn);

    // QKV projection -> fp16
    mma_gemm_kernel<0><<<dim3(QKVW / 128, NROWS / 128), 256, SMG_TOTAL>>>(
        xn, wqkv, nullptr, qkv, CC, QKVW, nullptr, nullptr);

    // causal attention (fp16 in/out)
    attn_kernel<<<dim3(4, HH, BB), 256, 65792>>>(qkv, o);

    // output projection + bias + residual -> f32
    mma_gemm_kernel<1><<<dim3(CC / 128, NROWS / 128), 256, SMG_TOTAL>>>(
        o, wo, x1, nullptr, CC, CC, bo, x);

    // LN2
    ln_kernel<<<NROWS, 128>>>(x1, g2, be2, xn2);

    // MLP up + ReLU -> fp16
    mma_gemm_kernel<2><<<dim3(FFN / 128, NROWS / 128), 256, SMG_TOTAL>>>(
        xn2, w1, nullptr, hb, CC, FFN, b1, nullptr);

    // MLP down + bias + residual -> out (f32)
    mma_gemm_kernel<1><<<dim3(CC / 128, NROWS / 128), 256, SMG_TOTAL>>>(
        hb, w2, out, nullptr, FFN, CC, b2, x1);
}

// round 5
// speedup vs baseline: 5.8440x; 1.3745x over previous
#include <cuda_runtime.h>
#include <cuda_fp16.h>
#include <math.h>
#include <stdint.h>

// Problem constants
#define BB   128
#define TT   256
#define CC   384
#define HH   6
#define DD   64
#define NROWS (BB*TT)          // 32768
#define QKVW  (3*CC)           // 1152
#define FFN   (4*CC)           // 1536
#define LN_EPS 1e-5f
#define ATT_SCALE 0.05103103630798287f   // 384^-0.5

typedef __half half_t;

// ---------------------------------------------------------------------------
// Scratch (device globals; allocation is forbidden)
// ---------------------------------------------------------------------------
__device__ half_t g_xn  [(size_t)NROWS*CC];
__device__ half_t g_qkv [(size_t)NROWS*QKVW];
__device__ half_t g_o   [(size_t)NROWS*CC];
__device__ float  g_x1  [(size_t)NROWS*CC];
__device__ half_t g_xn2 [(size_t)NROWS*CC];
__device__ half_t g_h   [(size_t)NROWS*FFN];
// packed weights, [N, K] K-major fp16
__device__ half_t g_wqkv[(size_t)QKVW*CC];
__device__ half_t g_wo  [(size_t)CC*CC];
__device__ half_t g_w1  [(size_t)FFN*CC];
__device__ half_t g_w2  [(size_t)CC*FFN];

// ---------------------------------------------------------------------------
// Helpers
// ---------------------------------------------------------------------------
__device__ __forceinline__ uint32_t smem_u32(const void* p) {
    return (uint32_t)__cvta_generic_to_shared(p);
}

#define CP_ASYNC16(dst, src) \
    asm volatile("cp.async.cg.shared.global [%0], [%1], 16;" :: "r"(dst), "l"(src))
#define CP_COMMIT() asm volatile("cp.async.commit_group;" ::: "memory")
#define CP_WAIT(n)  asm volatile("cp.async.wait_group %0;" :: "n"(n) : "memory")

#define LDSM_X4(r0, r1, r2, r3, addr) \
    asm volatile("ldmatrix.sync.aligned.m8n8.x4.shared.b16 {%0,%1,%2,%3}, [%4];" \
        : "=r"(r0), "=r"(r1), "=r"(r2), "=r"(r3) : "r"(addr))

#define LDSM_X4_T(r0, r1, r2, r3, addr) \
    asm volatile("ldmatrix.sync.aligned.m8n8.x4.trans.shared.b16 {%0,%1,%2,%3}, [%4];" \
        : "=r"(r0), "=r"(r1), "=r"(r2), "=r"(r3) : "r"(addr))

#define MMA_F16(d0, d1, d2, d3, a0, a1, a2, a3, b0, b1) \
    asm volatile("mma.sync.aligned.m16n8k16.row.col.f32.f16.f16.f32 " \
        "{%0,%1,%2,%3}, {%4,%5,%6,%7}, {%8,%9}, {%0,%1,%2,%3};" \
        : "+f"(d0), "+f"(d1), "+f"(d2), "+f"(d3) \
        : "r"(a0), "r"(a1), "r"(a2), "r"(a3), "r"(b0), "r"(b1))

__device__ __forceinline__ uint32_t pack_h2(float a, float b) {
    __half2 h = __floats2half2_rn(a, b);
    return *(uint32_t*)&h;
}

// ---------------------------------------------------------------------------
// Weight prep
// ---------------------------------------------------------------------------
__global__ void pack_wqkv_kernel(const float* __restrict__ Wq,
                                 const float* __restrict__ Wk,
                                 const float* __restrict__ Wv,
                                 half_t* __restrict__ out)
{
    int idx = blockIdx.x * 256 + threadIdx.x;
    if (idx >= QKVW * CC) return;
    int n = idx / CC, k = idx % CC;
    int proj = n / CC, hd = n % CC;
    int h = hd >> 6, d = hd & 63;
    const float* W = (proj == 0) ? Wq : ((proj == 1) ? Wk : Wv);
    out[idx] = __float2half(W[(size_t)(h * CC + k) * DD + d]);
}

// out[n*K+k] = W[k*N+n]
__global__ void transpose_pack_kernel(const float* __restrict__ W,
                                      half_t* __restrict__ out, int N, int K)
{
    int idx = blockIdx.x * 256 + threadIdx.x;
    if (idx >= N * K) return;
    int n = idx / K, k = idx % K;
    out[idx] = __float2half(W[(size_t)k * N + n]);
}

// ---------------------------------------------------------------------------
// LayerNorm with fp16 output
// ---------------------------------------------------------------------------
__global__ void __launch_bounds__(128) ln_kernel(const float* __restrict__ x,
                                                 const float* __restrict__ g,
                                                 const float* __restrict__ be,
                                                 half_t* __restrict__ out)
{
    const int row = blockIdx.x;
    const int tid = threadIdx.x;
    const float* xr = x + (size_t)row * CC;

    float v0 = xr[tid], v1 = xr[tid + 128], v2 = xr[tid + 256];
    float s  = v0 + v1 + v2;
    float sq = v0*v0 + v1*v1 + v2*v2;

    #pragma unroll
    for (int off = 16; off > 0; off >>= 1) {
        s  += __shfl_xor_sync(0xffffffffu, s,  off);
        sq += __shfl_xor_sync(0xffffffffu, sq, off);
    }
    __shared__ float ss[4], ssq[4];
    const int wid = tid >> 5, lane = tid & 31;
    if (lane == 0) { ss[wid] = s; ssq[wid] = sq; }
    __syncthreads();
    s  = ss[0]  + ss[1]  + ss[2]  + ss[3];
    sq = ssq[0] + ssq[1] + ssq[2] + ssq[3];

    const float mu  = s * (1.0f / CC);
    const float var = sq * (1.0f / CC) - mu * mu;
    const float inv = rsqrtf(var + LN_EPS);

    size_t rb = (size_t)row * CC;
    out[rb + tid      ] = __float2half((v0 - mu) * inv * g[tid      ] + be[tid      ]);
    out[rb + tid + 128] = __float2half((v1 - mu) * inv * g[tid + 128] + be[tid + 128]);
    out[rb + tid + 256] = __float2half((v2 - mu) * inv * g[tid + 256] + be[tid + 256]);
}

// ---------------------------------------------------------------------------
// fp16 HMMA GEMM (unchanged from R4).
// ---------------------------------------------------------------------------
#define RPAD 144
#define T_A  0
#define T_B  (128*RPAD)
#define BUFSZ (2*128*RPAD)
#define SMG_TOTAL (2*BUFSZ)

__device__ __forceinline__ void prefetch_chunk(
    uint32_t sbuf, const half_t* __restrict__ A, const half_t* __restrict__ B,
    int row0, int col0, int K, int k0, int tid)
{
    #pragma unroll
    for (int i = 0; i < 8; i++) {
        int idx = tid + i * 256;
        int r = idx >> 3, cp = idx & 7;
        if (r < 128) {
            CP_ASYNC16(sbuf + T_A + (uint32_t)(r * RPAD + cp * 16),
                       A + (size_t)(row0 + r) * K + k0 + cp * 8);
        } else {
            int rr = r - 128;
            CP_ASYNC16(sbuf + T_B + (uint32_t)(rr * RPAD + cp * 16),
                       B + (size_t)(col0 + rr) * K + k0 + cp * 8);
        }
    }
}

template <int EPI>
__global__ void __launch_bounds__(256)
mma_gemm_kernel(const half_t* __restrict__ A, const half_t* __restrict__ B,
                float* __restrict__ Cf, half_t* __restrict__ Ch,
                int K, int M,
                const float* __restrict__ bias, const float* __restrict__ res)
{
    extern __shared__ char sm[];
    const uint32_t sbase = smem_u32(sm);
    const int tid  = threadIdx.x;
    const int warp = tid >> 5, lane = tid & 31;
    const int wrow = warp >> 2, wcol = warp & 3;
    const int row0 = blockIdx.y * 128;
    const int col0 = blockIdx.x * 128;

    const int quad = lane >> 3, il = lane & 7;
    const uint32_t aoff = (uint32_t)((wrow * 64 + (quad & 1) * 8 + il) * RPAD
                                     + (quad >> 1) * 16);
    const uint32_t boff = (uint32_t)((wcol * 32 + (quad >> 1) * 8 + il) * RPAD
                                     + (quad & 1) * 16);

    float acc[4][4][4];
    #pragma unroll
    for (int m = 0; m < 4; m++)
        #pragma unroll
        for (int n = 0; n < 4; n++)
            #pragma unroll
            for (int k = 0; k < 4; k++) acc[m][n][k] = 0.0f;

    const int nch = K >> 6;
    prefetch_chunk(sbase, A, B, row0, col0, K, 0, tid);
    CP_COMMIT();

    for (int ch = 0; ch < nch; ch++) {
        if (ch + 1 < nch) {
            prefetch_chunk(sbase + ((ch + 1) & 1) * BUFSZ, A, B,
                           row0, col0, K, (ch + 1) << 6, tid);
            CP_COMMIT();
            CP_WAIT(1);
        } else {
            CP_WAIT(0);
        }
        __syncthreads();

        const uint32_t sbuf = sbase + (ch & 1) * BUFSZ;
        #pragma unroll
        for (int ks = 0; ks < 4; ks++) {
            const uint32_t ksb = ks * 32;
            uint32_t b[8];
            LDSM_X4(b[0], b[1], b[2], b[3], sbuf + T_B + boff + ksb);
            LDSM_X4(b[4], b[5], b[6], b[7], sbuf + T_B + boff + ksb + 16 * RPAD);

            #pragma unroll
            for (int mt = 0; mt < 4; mt++) {
                uint32_t a[4];
                LDSM_X4(a[0], a[1], a[2], a[3],
                        sbuf + T_A + aoff + mt * 16 * RPAD + ksb);
                #pragma unroll
                for (int nt = 0; nt < 4; nt++) {
                    float* d = acc[mt][nt];
                    MMA_F16(d[0], d[1], d[2], d[3],
                            a[0], a[1], a[2], a[3], b[nt*2], b[nt*2+1]);
                }
            }
        }
        __syncthreads();
    }

    const int r_l = lane >> 2;
    const int c_l = (lane & 3) << 1;
    #pragma unroll
    for (int mt = 0; mt < 4; mt++) {
        #pragma unroll
        for (int nt = 0; nt < 4; nt++) {
            const int r = row0 + wrow * 64 + mt * 16 + r_l;
            const int c = col0 + wcol * 32 + nt * 8 + c_l;
            const float* d = acc[mt][nt];
            #pragma unroll
            for (int half_i = 0; half_i < 2; half_i++) {
                const int rr = r + half_i * 8;
                const size_t off = (size_t)rr * M + c;
                float v0 = d[half_i * 2], v1 = d[half_i * 2 + 1];
                if (EPI == 0) {
                    *(__half2*)&Ch[off] = __floats2half2_rn(v0, v1);
                } else if (EPI == 1) {
                    float2 rv = *(const float2*)&res[off];
                    *(float2*)&Cf[off] = make_float2(v0 + bias[c] + rv.x,
                                                     v1 + bias[c + 1] + rv.y);
                } else {
                    v0 = fmaxf(v0 + bias[c],     0.0f);
                    v1 = fmaxf(v1 + bias[c + 1], 0.0f);
                    *(__half2*)&Ch[off] = __floats2half2_rn(v0, v1);
                }
            }
        }
    }
}

// ---------------------------------------------------------------------------
// Tensor-core causal flash attention.
// CTA = (q-tile 64, head, batch); 4 warps; warp owns 16 q-rows x all 64 keys.
// Q a-frags register-resident; S = Q K^T via HMMA; register online softmax;
// P accumulator layout == A-operand layout (free repack); PV via HMMA with
// trans-ldmatrix V fragments. fp32 softmax/accumulators, fp16 MMA operands.
// ---------------------------------------------------------------------------
#define ARPAD 144
__global__ void __launch_bounds__(128) attn_kernel(const half_t* __restrict__ qkv,
                                                   half_t* __restrict__ o)
{
    __shared__ char smem[3 * 64 * ARPAD];     // Q | K | V tiles, 27648 B
    const uint32_t sb = smem_u32(smem);
    const uint32_t Kb = sb + 64 * ARPAD;
    const uint32_t Vb = sb + 128 * ARPAD;

    const int qt = blockIdx.x;
    const int h  = blockIdx.y;
    const int b  = blockIdx.z;
    const int tid  = threadIdx.x;
    const int warp = tid >> 5, lane = tid & 31;
    const int quad = lane >> 3, il = lane & 7;
    const int r_l  = lane >> 2, c_l = (lane & 3) << 1;

    const size_t qrow0 = (size_t)(b * TT + qt * 64);
    const half_t* qg = qkv + qrow0 * QKVW + h * 64;

    // stage Q (64x64 fp16 -> smem, 16B per cp)
    #pragma unroll
    for (int i = 0; i < 4; i++) {
        int idx = tid + i * 128;
        int r = idx >> 3, cp = idx & 7;
        CP_ASYNC16(sb + (uint32_t)(r * ARPAD + cp * 16),
                   qg + (size_t)r * QKVW + cp * 8);
    }
    CP_COMMIT();
    CP_WAIT(0);
    __syncthreads();

    // Q A-fragments (rows warp*16..+15, k=64 -> 4 ksteps)
    uint32_t qa[4][4];
    {
        const uint32_t aoff = sb + (uint32_t)((warp * 16 + (quad & 1) * 8 + il) * ARPAD
                                              + (quad >> 1) * 16);
        #pragma unroll
        for (int ks = 0; ks < 4; ks++)
            LDSM_X4(qa[ks][0], qa[ks][1], qa[ks][2], qa[ks][3], aoff + ks * 32);
    }

    float m0 = -1e30f, m1 = -1e30f, l0 = 0.0f, l1 = 0.0f;
    float oacc[8][4];
    #pragma unroll
    for (int nt = 0; nt < 8; nt++)
        #pragma unroll
        for (int j = 0; j < 4; j++) oacc[nt][j] = 0.0f;

    // shared lane offsets
    const uint32_t koff = Kb + (uint32_t)(((quad >> 1) * 8 + il) * ARPAD + (quad & 1) * 16);
    const uint32_t voff = Vb + (uint32_t)(((quad & 1) * 8 + il) * ARPAD + (quad >> 1) * 16);

    const int lrow0 = warp * 16 + r_l;       // local q row (0..63) of this thread
    const int lrow1 = lrow0 + 8;

    for (int jt = 0; jt <= qt; jt++) {
        __syncthreads();                     // prev PV reads of V done
        {
            const half_t* kg = qkv + (size_t)(b * TT + jt * 64) * QKVW + CC + h * 64;
            const half_t* vg = kg + CC;
            #pragma unroll
            for (int i = 0; i < 4; i++) {
                int idx = tid + i * 128;
                int r = idx >> 3, cp = idx & 7;
                CP_ASYNC16(Kb + (uint32_t)(r * ARPAD + cp * 16),
                           kg + (size_t)r * QKVW + cp * 8);
                CP_ASYNC16(Vb + (uint32_t)(r * ARPAD + cp * 16),
                           vg + (size_t)r * QKVW + cp * 8);
            }
        }
        CP_COMMIT();
        CP_WAIT(0);
        __syncthreads();

        // S = Q K^T : 8 n-tiles x 4 ksteps
        float s[8][4];
        #pragma unroll
        for (int nt = 0; nt < 8; nt++)
            #pragma unroll
            for (int j = 0; j < 4; j++) s[nt][j] = 0.0f;

        #pragma unroll
        for (int np = 0; np < 4; np++) {
            #pragma unroll
            for (int ks = 0; ks < 4; ks++) {
                uint32_t bb[4];
                LDSM_X4(bb[0], bb[1], bb[2], bb[3],
                        koff + np * 16 * ARPAD + ks * 32);
                MMA_F16(s[2*np][0],   s[2*np][1],   s[2*np][2],   s[2*np][3],
                        qa[ks][0], qa[ks][1], qa[ks][2], qa[ks][3], bb[0], bb[1]);
                MMA_F16(s[2*np+1][0], s[2*np+1][1], s[2*np+1][2], s[2*np+1][3],
                        qa[ks][0], qa[ks][1], qa[ks][2], qa[ks][3], bb[2], bb[3]);
            }
        }

        // scale + causal mask (diagonal tile only)
        if (jt == qt) {
            #pragma unroll
            for (int nt = 0; nt < 8; nt++) {
                int col0c = nt * 8 + c_l;
                s[nt][0] = (col0c     > lrow0) ? -1e30f : s[nt][0] * ATT_SCALE;
                s[nt][1] = (col0c + 1 > lrow0) ? -1e30f : s[nt][1] * ATT_SCALE;
                s[nt][2] = (col0c     > lrow1) ? -1e30f : s[nt][2] * ATT_SCALE;
                s[nt][3] = (col0c + 1 > lrow1) ? -1e30f : s[nt][3] * ATT_SCALE;
            }
        } else {
            #pragma unroll
            for (int nt = 0; nt < 8; nt++)
                #pragma unroll
                for (int j = 0; j < 4; j++) s[nt][j] *= ATT_SCALE;
        }

        // online softmax (rows lrow0, lrow1; reduce across quad lanes)
        float mx0 = -1e30f, mx1 = -1e30f;
        #pragma unroll
        for (int nt = 0; nt < 8; nt++) {
            mx0 = fmaxf(mx0, fmaxf(s[nt][0], s[nt][1]));
            mx1 = fmaxf(mx1, fmaxf(s[nt][2], s[nt][3]));
        }
        mx0 = fmaxf(mx0, __shfl_xor_sync(0xffffffffu, mx0, 1));
        mx0 = fmaxf(mx0, __shfl_xor_sync(0xffffffffu, mx0, 2));
        mx1 = fmaxf(mx1, __shfl_xor_sync(0xffffffffu, mx1, 1));
        mx1 = fmaxf(mx1, __shfl_xor_sync(0xffffffffu, mx1, 2));

        const float nm0 = fmaxf(m0, mx0), nm1 = fmaxf(m1, mx1);
        const float fac0 = __expf(m0 - nm0), fac1 = __expf(m1 - nm1);
        m0 = nm0; m1 = nm1;

        float ps0 = 0.0f, ps1 = 0.0f;
        #pragma unroll
        for (int nt = 0; nt < 8; nt++) {
            s[nt][0] = __expf(s[nt][0] - nm0);
            s[nt][1] = __expf(s[nt][1] - nm0);
            s[nt][2] = __expf(s[nt][2] - nm1);
            s[nt][3] = __expf(s[nt][3] - nm1);
            ps0 += s[nt][0] + s[nt][1];
            ps1 += s[nt][2] + s[nt][3];
        }
        ps0 += __shfl_xor_sync(0xffffffffu, ps0, 1);
        ps0 += __shfl_xor_sync(0xffffffffu, ps0, 2);
        ps1 += __shfl_xor_sync(0xffffffffu, ps1, 1);
        ps1 += __shfl_xor_sync(0xffffffffu, ps1, 2);
        l0 = l0 * fac0 + ps0;
        l1 = l1 * fac1 + ps1;

        #pragma unroll
        for (int nt = 0; nt < 8; nt++) {
            oacc[nt][0] *= fac0; oacc[nt][1] *= fac0;
            oacc[nt][2] *= fac1; oacc[nt][3] *= fac1;
        }

        // O += P V  (P c-layout == A-operand layout per kstep pair)
        #pragma unroll
        for (int ks = 0; ks < 4; ks++) {
            uint32_t pa[4];
            pa[0] = pack_h2(s[2*ks][0],   s[2*ks][1]);
            pa[1] = pack_h2(s[2*ks][2],   s[2*ks][3]);
            pa[2] = pack_h2(s[2*ks+1][0], s[2*ks+1][1]);
            pa[3] = pack_h2(s[2*ks+1][2], s[2*ks+1][3]);
            #pragma unroll
            for (int np = 0; np < 4; np++) {
                uint32_t vb[4];
                LDSM_X4_T(vb[0], vb[1], vb[2], vb[3],
                          voff + ks * 16 * ARPAD + np * 32);
                MMA_F16(oacc[2*np][0],   oacc[2*np][1],   oacc[2*np][2],   oacc[2*np][3],
                        pa[0], pa[1], pa[2], pa[3], vb[0], vb[1]);
                MMA_F16(oacc[2*np+1][0], oacc[2*np+1][1], oacc[2*np+1][2], oacc[2*np+1][3],
                        pa[0], pa[1], pa[2], pa[3], vb[2], vb[3]);
            }
        }
    }

    // normalize + write (concat-heads fp16 layout)
    const float inv0 = 1.0f / l0, inv1 = 1.0f / l1;
    half_t* og = o + (qrow0 + warp * 16) * CC + h * 64;
    #pragma unroll
    for (int nt = 0; nt < 8; nt++) {
        const int col = nt * 8 + c_l;
        *(__half2*)&og[(size_t)r_l * CC + col] =
            __floats2half2_rn(oacc[nt][0] * inv0, oacc[nt][1] * inv0);
        *(__half2*)&og[(size_t)(r_l + 8) * CC + col] =
            __floats2half2_rn(oacc[nt][2] * inv1, oacc[nt][3] * inv1);
    }
}

// ---------------------------------------------------------------------------
// Launch
// ---------------------------------------------------------------------------
extern "C" void kernel_launch(void* const* d_in, const int* in_sizes, int n_in,
                              void* d_out, int out_size)
{
    const float* x   = (const float*)d_in[0];
    const float* Wq  = (const float*)d_in[1];
    const float* Wk  = (const float*)d_in[2];
    const float* Wv  = (const float*)d_in[3];
    const float* Wo  = (const float*)d_in[4];
    const float* bo  = (const float*)d_in[5];
    const float* W1  = (const float*)d_in[6];
    const float* b1  = (const float*)d_in[7];
    const float* W2  = (const float*)d_in[8];
    const float* b2  = (const float*)d_in[9];
    const float* g1  = (const float*)d_in[10];
    const float* be1 = (const float*)d_in[11];
    const float* g2  = (const float*)d_in[12];
    const float* be2 = (const float*)d_in[13];
    float* out = (float*)d_out;

    half_t *xn, *qkv, *o, *xn2, *hb, *wqkv, *wo, *w1, *w2;
    float *x1;
    cudaGetSymbolAddress((void**)&xn,   g_xn);
    cudaGetSymbolAddress((void**)&qkv,  g_qkv);
    cudaGetSymbolAddress((void**)&o,    g_o);
    cudaGetSymbolAddress((void**)&x1,   g_x1);
    cudaGetSymbolAddress((void**)&xn2,  g_xn2);
    cudaGetSymbolAddress((void**)&hb,   g_h);
    cudaGetSymbolAddress((void**)&wqkv, g_wqkv);
    cudaGetSymbolAddress((void**)&wo,   g_wo);
    cudaGetSymbolAddress((void**)&w1,   g_w1);
    cudaGetSymbolAddress((void**)&w2,   g_w2);

    cudaFuncSetAttribute(mma_gemm_kernel<0>,
                         cudaFuncAttributeMaxDynamicSharedMemorySize, SMG_TOTAL);
    cudaFuncSetAttribute(mma_gemm_kernel<1>,
                         cudaFuncAttributeMaxDynamicSharedMemorySize, SMG_TOTAL);
    cudaFuncSetAttribute(mma_gemm_kernel<2>,
                         cudaFuncAttributeMaxDynamicSharedMemorySize, SMG_TOTAL);

    // weight prep
    pack_wqkv_kernel<<<(QKVW * CC + 255) / 256, 256>>>(Wq, Wk, Wv, wqkv);
    transpose_pack_kernel<<<(CC * CC + 255) / 256, 256>>>(Wo, wo, CC, CC);
    transpose_pack_kernel<<<(FFN * CC + 255) / 256, 256>>>(W1, w1, FFN, CC);
    transpose_pack_kernel<<<(CC * FFN + 255) / 256, 256>>>(W2, w2, CC, FFN);

    // LN1
    ln_kernel<<<NROWS, 128>>>(x, g1, be1, xn);

    // QKV projection -> fp16
    mma_gemm_kernel<0><<<dim3(QKVW / 128, NROWS / 128), 256, SMG_TOTAL>>>(
        xn, wqkv, nullptr, qkv, CC, QKVW, nullptr, nullptr);

    // causal attention (tensor cores)
    attn_kernel<<<dim3(4, HH, BB), 128>>>(qkv, o);

    // output projection + bias + residual -> f32
    mma_gemm_kernel<1><<<dim3(CC / 128, NROWS / 128), 256, SMG_TOTAL>>>(
        o, wo, x1, nullptr, CC, CC, bo, x);

    // LN2
    ln_kernel<<<NROWS, 128>>>(x1, g2, be2, xn2);

    // MLP up + ReLU -> fp16
    mma_gemm_kernel<2><<<dim3(FFN / 128, NROWS / 128), 256, SMG_TOTAL>>>(
        xn2, w1, nullptr, hb, CC, FFN, b1, nullptr);

    // MLP down + bias + residual -> out (f32)
    mma_gemm_kernel<1><<<dim3(CC / 128, NROWS / 128), 256, SMG_TOTAL>>>(
        hb, w2, out, nullptr, FFN, CC, b2, x1);
}

// round 6
// speedup vs baseline: 6.1247x; 1.0480x over previous
#include <cuda_runtime.h>
#include <cuda_fp16.h>
#include <math.h>
#include <stdint.h>

// Problem constants
#define BB   128
#define TT   256
#define CC   384
#define HH   6
#define DD   64
#define NROWS (BB*TT)          // 32768
#define QKVW  (3*CC)           // 1152
#define FFN   (4*CC)           // 1536
#define LN_EPS 1e-5f
#define ATT_SCALE 0.05103103630798287f   // 384^-0.5

typedef __half half_t;

// ---------------------------------------------------------------------------
// Scratch (device globals; allocation is forbidden)
// ---------------------------------------------------------------------------
__device__ half_t g_xn  [(size_t)NROWS*CC];
__device__ half_t g_qkv [(size_t)NROWS*QKVW];
__device__ half_t g_o   [(size_t)NROWS*CC];
__device__ float  g_x1  [(size_t)NROWS*CC];
__device__ half_t g_xn2 [(size_t)NROWS*CC];
__device__ half_t g_h   [(size_t)NROWS*FFN];
// packed weights, [N, K] K-major fp16
__device__ half_t g_wqkv[(size_t)QKVW*CC];
__device__ half_t g_wo  [(size_t)CC*CC];
__device__ half_t g_w1  [(size_t)FFN*CC];
__device__ half_t g_w2  [(size_t)CC*FFN];

// ---------------------------------------------------------------------------
// Helpers
// ---------------------------------------------------------------------------
__device__ __forceinline__ uint32_t smem_u32(const void* p) {
    return (uint32_t)__cvta_generic_to_shared(p);
}

#define CP_ASYNC16(dst, src) \
    asm volatile("cp.async.cg.shared.global [%0], [%1], 16;" :: "r"(dst), "l"(src))
#define CP_COMMIT() asm volatile("cp.async.commit_group;" ::: "memory")
#define CP_WAIT(n)  asm volatile("cp.async.wait_group %0;" :: "n"(n) : "memory")

#define LDSM_X4(r0, r1, r2, r3, addr) \
    asm volatile("ldmatrix.sync.aligned.m8n8.x4.shared.b16 {%0,%1,%2,%3}, [%4];" \
        : "=r"(r0), "=r"(r1), "=r"(r2), "=r"(r3) : "r"(addr))

#define LDSM_X4_T(r0, r1, r2, r3, addr) \
    asm volatile("ldmatrix.sync.aligned.m8n8.x4.trans.shared.b16 {%0,%1,%2,%3}, [%4];" \
        : "=r"(r0), "=r"(r1), "=r"(r2), "=r"(r3) : "r"(addr))

#define MMA_F16(d0, d1, d2, d3, a0, a1, a2, a3, b0, b1) \
    asm volatile("mma.sync.aligned.m16n8k16.row.col.f32.f16.f16.f32 " \
        "{%0,%1,%2,%3}, {%4,%5,%6,%7}, {%8,%9}, {%0,%1,%2,%3};" \
        : "+f"(d0), "+f"(d1), "+f"(d2), "+f"(d3) \
        : "r"(a0), "r"(a1), "r"(a2), "r"(a3), "r"(b0), "r"(b1))

__device__ __forceinline__ uint32_t pack_h2(float a, float b) {
    __half2 h = __floats2half2_rn(a, b);
    return *(uint32_t*)&h;
}

// ---------------------------------------------------------------------------
// Combined weight prep (one launch for all four weight tensors)
//   seg 0: Wqkv pack  [QKVW, CC]   from Wq/Wk/Wv [H,C,D]
//   seg 1: Wo^T       [CC, CC]
//   seg 2: W1^T       [FFN, CC]
//   seg 3: W2^T       [CC, FFN]
// ---------------------------------------------------------------------------
#define NW_QKV (QKVW*CC)           // 442368
#define NW_O   (CC*CC)             // 147456
#define NW_1   (FFN*CC)            // 589824
#define NW_2   (CC*FFN)            // 589824
#define NW_TOT (NW_QKV+NW_O+NW_1+NW_2)

__global__ void pack_all_kernel(const float* __restrict__ Wq,
                                const float* __restrict__ Wk,
                                const float* __restrict__ Wv,
                                const float* __restrict__ Wo,
                                const float* __restrict__ W1,
                                const float* __restrict__ W2,
                                half_t* __restrict__ wqkv,
                                half_t* __restrict__ wo,
                                half_t* __restrict__ w1,
                                half_t* __restrict__ w2)
{
    int idx = blockIdx.x * 256 + threadIdx.x;
    if (idx < NW_QKV) {
        int n = idx / CC, k = idx % CC;
        int proj = n / CC, hd = n % CC;
        int h = hd >> 6, d = hd & 63;
        const float* W = (proj == 0) ? Wq : ((proj == 1) ? Wk : Wv);
        wqkv[idx] = __float2half(W[(size_t)(h * CC + k) * DD + d]);
        return;
    }
    idx -= NW_QKV;
    if (idx < NW_O) {
        int n = idx / CC, k = idx % CC;
        wo[idx] = __float2half(Wo[(size_t)k * CC + n]);
        return;
    }
    idx -= NW_O;
    if (idx < NW_1) {
        int n = idx / CC, k = idx % CC;
        w1[idx] = __float2half(W1[(size_t)k * FFN + n]);
        return;
    }
    idx -= NW_1;
    if (idx < NW_2) {
        int n = idx / FFN, k = idx % FFN;
        w2[idx] = __float2half(W2[(size_t)k * CC + n]);
    }
}

// ---------------------------------------------------------------------------
// LayerNorm with fp16 output
// ---------------------------------------------------------------------------
__global__ void __launch_bounds__(128) ln_kernel(const float* __restrict__ x,
                                                 const float* __restrict__ g,
                                                 const float* __restrict__ be,
                                                 half_t* __restrict__ out)
{
    const int row = blockIdx.x;
    const int tid = threadIdx.x;
    const float* xr = x + (size_t)row * CC;

    float v0 = xr[tid], v1 = xr[tid + 128], v2 = xr[tid + 256];
    float s  = v0 + v1 + v2;
    float sq = v0*v0 + v1*v1 + v2*v2;

    #pragma unroll
    for (int off = 16; off > 0; off >>= 1) {
        s  += __shfl_xor_sync(0xffffffffu, s,  off);
        sq += __shfl_xor_sync(0xffffffffu, sq, off);
    }
    __shared__ float ss[4], ssq[4];
    const int wid = tid >> 5, lane = tid & 31;
    if (lane == 0) { ss[wid] = s; ssq[wid] = sq; }
    __syncthreads();
    s  = ss[0]  + ss[1]  + ss[2]  + ss[3];
    sq = ssq[0] + ssq[1] + ssq[2] + ssq[3];

    const float mu  = s * (1.0f / CC);
    const float var = sq * (1.0f / CC) - mu * mu;
    const float inv = rsqrtf(var + LN_EPS);

    size_t rb = (size_t)row * CC;
    out[rb + tid      ] = __float2half((v0 - mu) * inv * g[tid      ] + be[tid      ]);
    out[rb + tid + 128] = __float2half((v1 - mu) * inv * g[tid + 128] + be[tid + 128]);
    out[rb + tid + 256] = __float2half((v2 - mu) * inv * g[tid + 256] + be[tid + 256]);
}

// ---------------------------------------------------------------------------
// fp16 HMMA GEMM, 3-stage cp.async pipeline.
// CTA tile 128x128, 8 warps (2x4), warp tile 64x32, K-chunks of 64.
//   EPI 0: fp16 out   EPI 1: +bias+res -> f32   EPI 2: relu(+bias) -> fp16
// ---------------------------------------------------------------------------
#define RPAD 144
#define T_A  0
#define T_B  (128*RPAD)
#define BUFSZ (2*128*RPAD)            // 36864 per stage
#define NSTAGE 3
#define SMG_TOTAL (NSTAGE*BUFSZ)      // 110592

__device__ __forceinline__ void prefetch_chunk(
    uint32_t sbuf, const half_t* __restrict__ A, const half_t* __restrict__ B,
    int row0, int col0, int K, int k0, int tid)
{
    #pragma unroll
    for (int i = 0; i < 8; i++) {
        int idx = tid + i * 256;
        int r = idx >> 3, cp = idx & 7;
        if (r < 128) {
            CP_ASYNC16(sbuf + T_A + (uint32_t)(r * RPAD + cp * 16),
                       A + (size_t)(row0 + r) * K + k0 + cp * 8);
        } else {
            int rr = r - 128;
            CP_ASYNC16(sbuf + T_B + (uint32_t)(rr * RPAD + cp * 16),
                       B + (size_t)(col0 + rr) * K + k0 + cp * 8);
        }
    }
}

template <int EPI>
__global__ void __launch_bounds__(256)
mma_gemm_kernel(const half_t* __restrict__ A, const half_t* __restrict__ B,
                float* __restrict__ Cf, half_t* __restrict__ Ch,
                int K, int M,
                const float* __restrict__ bias, const float* __restrict__ res)
{
    extern __shared__ char sm[];
    const uint32_t sbase = smem_u32(sm);
    const int tid  = threadIdx.x;
    const int warp = tid >> 5, lane = tid & 31;
    const int wrow = warp >> 2, wcol = warp & 3;
    const int row0 = blockIdx.y * 128;
    const int col0 = blockIdx.x * 128;

    const int quad = lane >> 3, il = lane & 7;
    const uint32_t aoff = (uint32_t)((wrow * 64 + (quad & 1) * 8 + il) * RPAD
                                     + (quad >> 1) * 16);
    const uint32_t boff = (uint32_t)((wcol * 32 + (quad >> 1) * 8 + il) * RPAD
                                     + (quad & 1) * 16);

    float acc[4][4][4];
    #pragma unroll
    for (int m = 0; m < 4; m++)
        #pragma unroll
        for (int n = 0; n < 4; n++)
            #pragma unroll
            for (int k = 0; k < 4; k++) acc[m][n][k] = 0.0f;

    const int nch = K >> 6;   // always >= 6 here

    // prologue: stages 0 and 1 in flight
    prefetch_chunk(sbase, A, B, row0, col0, K, 0, tid);
    CP_COMMIT();
    prefetch_chunk(sbase + BUFSZ, A, B, row0, col0, K, 64, tid);
    CP_COMMIT();

    int sread = 0, swrite = 2;
    for (int ch = 0; ch < nch; ch++) {
        if (ch + 1 < nch) { CP_WAIT(1); } else { CP_WAIT(0); }
        __syncthreads();     // chunk ch ready; compute(ch-1) retired by all warps

        if (ch + 2 < nch) {
            prefetch_chunk(sbase + swrite * BUFSZ, A, B,
                           row0, col0, K, (ch + 2) << 6, tid);
            CP_COMMIT();
            swrite = (swrite + 1 == NSTAGE) ? 0 : swrite + 1;
        }

        const uint32_t sbuf = sbase + sread * BUFSZ;
        sread = (sread + 1 == NSTAGE) ? 0 : sread + 1;

        #pragma unroll
        for (int ks = 0; ks < 4; ks++) {
            const uint32_t ksb = ks * 32;
            uint32_t b[8];
            LDSM_X4(b[0], b[1], b[2], b[3], sbuf + T_B + boff + ksb);
            LDSM_X4(b[4], b[5], b[6], b[7], sbuf + T_B + boff + ksb + 16 * RPAD);

            #pragma unroll
            for (int mt = 0; mt < 4; mt++) {
                uint32_t a[4];
                LDSM_X4(a[0], a[1], a[2], a[3],
                        sbuf + T_A + aoff + mt * 16 * RPAD + ksb);
                #pragma unroll
                for (int nt = 0; nt < 4; nt++) {
                    float* d = acc[mt][nt];
                    MMA_F16(d[0], d[1], d[2], d[3],
                            a[0], a[1], a[2], a[3], b[nt*2], b[nt*2+1]);
                }
            }
        }
    }

    const int r_l = lane >> 2;
    const int c_l = (lane & 3) << 1;
    #pragma unroll
    for (int mt = 0; mt < 4; mt++) {
        #pragma unroll
        for (int nt = 0; nt < 4; nt++) {
            const int r = row0 + wrow * 64 + mt * 16 + r_l;
            const int c = col0 + wcol * 32 + nt * 8 + c_l;
            const float* d = acc[mt][nt];
            #pragma unroll
            for (int half_i = 0; half_i < 2; half_i++) {
                const int rr = r + half_i * 8;
                const size_t off = (size_t)rr * M + c;
                float v0 = d[half_i * 2], v1 = d[half_i * 2 + 1];
                if (EPI == 0) {
                    *(__half2*)&Ch[off] = __floats2half2_rn(v0, v1);
                } else if (EPI == 1) {
                    float2 rv = *(const float2*)&res[off];
                    *(float2*)&Cf[off] = make_float2(v0 + bias[c] + rv.x,
                                                     v1 + bias[c + 1] + rv.y);
                } else {
                    v0 = fmaxf(v0 + bias[c],     0.0f);
                    v1 = fmaxf(v1 + bias[c + 1], 0.0f);
                    *(__half2*)&Ch[off] = __floats2half2_rn(v0, v1);
                }
            }
        }
    }
}

// ---------------------------------------------------------------------------
// Tensor-core causal flash attention with double-buffered K/V.
// CTA = (q-tile 64, head, batch); 4 warps; warp owns 16 q-rows x all 64 keys.
// ---------------------------------------------------------------------------
#define ARPAD 144
__global__ void __launch_bounds__(128) attn_kernel(const half_t* __restrict__ qkv,
                                                   half_t* __restrict__ o)
{
    __shared__ char smem[5 * 64 * ARPAD];     // Q | K0 V0 | K1 V1  = 46080 B
    const uint32_t sb  = smem_u32(smem);
    const uint32_t KV0 = sb + 64 * ARPAD;     // stage s at KV0 + s*2*64*ARPAD

    const int qt = blockIdx.x;
    const int h  = blockIdx.y;
    const int b  = blockIdx.z;
    const int tid  = threadIdx.x;
    const int warp = tid >> 5, lane = tid & 31;
    const int quad = lane >> 3, il = lane & 7;
    const int r_l  = lane >> 2, c_l = (lane & 3) << 1;

    const size_t qrow0 = (size_t)(b * TT + qt * 64);
    const half_t* qg = qkv + qrow0 * QKVW + h * 64;
    const half_t* kvg = qkv + (size_t)(b * TT) * QKVW + CC + h * 64;

    // stage Q
    #pragma unroll
    for (int i = 0; i < 4; i++) {
        int idx = tid + i * 128;
        int r = idx >> 3, cp = idx & 7;
        CP_ASYNC16(sb + (uint32_t)(r * ARPAD + cp * 16),
                   qg + (size_t)r * QKVW + cp * 8);
    }
    CP_COMMIT();

    // prefetch K/V tile 0 into stage 0
    #pragma unroll
    for (int i = 0; i < 4; i++) {
        int idx = tid + i * 128;
        int r = idx >> 3, cp = idx & 7;
        const half_t* kg = kvg + (size_t)r * QKVW + cp * 8;
        CP_ASYNC16(KV0 + (uint32_t)(r * ARPAD + cp * 16), kg);
        CP_ASYNC16(KV0 + (uint32_t)((64 + r) * ARPAD + cp * 16), kg + CC);
    }
    CP_COMMIT();

    // wait for Q (group of 2 pending; Q is the older) — just wait both minus kv
    CP_WAIT(1);
    __syncthreads();

    // Q A-fragments
    uint32_t qa[4][4];
    {
        const uint32_t aoff = sb + (uint32_t)((warp * 16 + (quad & 1) * 8 + il) * ARPAD
                                              + (quad >> 1) * 16);
        #pragma unroll
        for (int ks = 0; ks < 4; ks++)
            LDSM_X4(qa[ks][0], qa[ks][1], qa[ks][2], qa[ks][3], aoff + ks * 32);
    }

    float m0 = -1e30f, m1 = -1e30f, l0 = 0.0f, l1 = 0.0f;
    float oacc[8][4];
    #pragma unroll
    for (int nt = 0; nt < 8; nt++)
        #pragma unroll
        for (int j = 0; j < 4; j++) oacc[nt][j] = 0.0f;

    const uint32_t klane = (uint32_t)(((quad >> 1) * 8 + il) * ARPAD + (quad & 1) * 16);
    const uint32_t vlane = (uint32_t)(((quad & 1) * 8 + il) * ARPAD + (quad >> 1) * 16);

    const int lrow0 = warp * 16 + r_l;
    const int lrow1 = lrow0 + 8;

    for (int jt = 0; jt <= qt; jt++) {
        CP_WAIT(0);            // K/V tile jt resident
        __syncthreads();       // and compute(jt-1) retired by all warps

        // prefetch next tile into other stage
        if (jt < qt) {
            const uint32_t kvn = KV0 + ((jt + 1) & 1) * 2 * 64 * ARPAD;
            const half_t* kg0 = kvg + (size_t)((jt + 1) * 64) * QKVW;
            #pragma unroll
            for (int i = 0; i < 4; i++) {
                int idx = tid + i * 128;
                int r = idx >> 3, cp = idx & 7;
                const half_t* kg = kg0 + (size_t)r * QKVW + cp * 8;
                CP_ASYNC16(kvn + (uint32_t)(r * ARPAD + cp * 16), kg);
                CP_ASYNC16(kvn + (uint32_t)((64 + r) * ARPAD + cp * 16), kg + CC);
            }
            CP_COMMIT();
        }

        const uint32_t kvs = KV0 + (jt & 1) * 2 * 64 * ARPAD;
        const uint32_t koff = kvs + klane;
        const uint32_t voff = kvs + 64 * ARPAD + vlane;

        // S = Q K^T
        float s[8][4];
        #pragma unroll
        for (int nt = 0; nt < 8; nt++)
            #pragma unroll
            for (int j = 0; j < 4; j++) s[nt][j] = 0.0f;

        #pragma unroll
        for (int np = 0; np < 4; np++) {
            #pragma unroll
            for (int ks = 0; ks < 4; ks++) {
                uint32_t bb[4];
                LDSM_X4(bb[0], bb[1], bb[2], bb[3],
                        koff + np * 16 * ARPAD + ks * 32);
                MMA_F16(s[2*np][0],   s[2*np][1],   s[2*np][2],   s[2*np][3],
                        qa[ks][0], qa[ks][1], qa[ks][2], qa[ks][3], bb[0], bb[1]);
                MMA_F16(s[2*np+1][0], s[2*np+1][1], s[2*np+1][2], s[2*np+1][3],
                        qa[ks][0], qa[ks][1], qa[ks][2], qa[ks][3], bb[2], bb[3]);
            }
        }

        if (jt == qt) {
            #pragma unroll
            for (int nt = 0; nt < 8; nt++) {
                int col0c = nt * 8 + c_l;
                s[nt][0] = (col0c     > lrow0) ? -1e30f : s[nt][0] * ATT_SCALE;
                s[nt][1] = (col0c + 1 > lrow0) ? -1e30f : s[nt][1] * ATT_SCALE;
                s[nt][2] = (col0c     > lrow1) ? -1e30f : s[nt][2] * ATT_SCALE;
                s[nt][3] = (col0c + 1 > lrow1) ? -1e30f : s[nt][3] * ATT_SCALE;
            }
        } else {
            #pragma unroll
            for (int nt = 0; nt < 8; nt++)
                #pragma unroll
                for (int j = 0; j < 4; j++) s[nt][j] *= ATT_SCALE;
        }

        float mx0 = -1e30f, mx1 = -1e30f;
        #pragma unroll
        for (int nt = 0; nt < 8; nt++) {
            mx0 = fmaxf(mx0, fmaxf(s[nt][0], s[nt][1]));
            mx1 = fmaxf(mx1, fmaxf(s[nt][2], s[nt][3]));
        }
        mx0 = fmaxf(mx0, __shfl_xor_sync(0xffffffffu, mx0, 1));
        mx0 = fmaxf(mx0, __shfl_xor_sync(0xffffffffu, mx0, 2));
        mx1 = fmaxf(mx1, __shfl_xor_sync(0xffffffffu, mx1, 1));
        mx1 = fmaxf(mx1, __shfl_xor_sync(0xffffffffu, mx1, 2));

        const float nm0 = fmaxf(m0, mx0), nm1 = fmaxf(m1, mx1);
        const float fac0 = __expf(m0 - nm0), fac1 = __expf(m1 - nm1);
        m0 = nm0; m1 = nm1;

        float ps0 = 0.0f, ps1 = 0.0f;
        #pragma unroll
        for (int nt = 0; nt < 8; nt++) {
            s[nt][0] = __expf(s[nt][0] - nm0);
            s[nt][1] = __expf(s[nt][1] - nm0);
            s[nt][2] = __expf(s[nt][2] - nm1);
            s[nt][3] = __expf(s[nt][3] - nm1);
            ps0 += s[nt][0] + s[nt][1];
            ps1 += s[nt][2] + s[nt][3];
        }
        ps0 += __shfl_xor_sync(0xffffffffu, ps0, 1);
        ps0 += __shfl_xor_sync(0xffffffffu, ps0, 2);
        ps1 += __shfl_xor_sync(0xffffffffu, ps1, 1);
        ps1 += __shfl_xor_sync(0xffffffffu, ps1, 2);
        l0 = l0 * fac0 + ps0;
        l1 = l1 * fac1 + ps1;

        #pragma unroll
        for (int nt = 0; nt < 8; nt++) {
            oacc[nt][0] *= fac0; oacc[nt][1] *= fac0;
            oacc[nt][2] *= fac1; oacc[nt][3] *= fac1;
        }

        // O += P V
        #pragma unroll
        for (int ks = 0; ks < 4; ks++) {
            uint32_t pa[4];
            pa[0] = pack_h2(s[2*ks][0],   s[2*ks][1]);
            pa[1] = pack_h2(s[2*ks][2],   s[2*ks][3]);
            pa[2] = pack_h2(s[2*ks+1][0], s[2*ks+1][1]);
            pa[3] = pack_h2(s[2*ks+1][2], s[2*ks+1][3]);
            #pragma unroll
            for (int np = 0; np < 4; np++) {
                uint32_t vb[4];
                LDSM_X4_T(vb[0], vb[1], vb[2], vb[3],
                          voff + ks * 16 * ARPAD + np * 32);
                MMA_F16(oacc[2*np][0],   oacc[2*np][1],   oacc[2*np][2],   oacc[2*np][3],
                        pa[0], pa[1], pa[2], pa[3], vb[0], vb[1]);
                MMA_F16(oacc[2*np+1][0], oacc[2*np+1][1], oacc[2*np+1][2], oacc[2*np+1][3],
                        pa[0], pa[1], pa[2], pa[3], vb[2], vb[3]);
            }
        }
    }

    const float inv0 = 1.0f / l0, inv1 = 1.0f / l1;
    half_t* og = o + (qrow0 + warp * 16) * CC + h * 64;
    #pragma unroll
    for (int nt = 0; nt < 8; nt++) {
        const int col = nt * 8 + c_l;
        *(__half2*)&og[(size_t)r_l * CC + col] =
            __floats2half2_rn(oacc[nt][0] * inv0, oacc[nt][1] * inv0);
        *(__half2*)&og[(size_t)(r_l + 8) * CC + col] =
            __floats2half2_rn(oacc[nt][2] * inv1, oacc[nt][3] * inv1);
    }
}

// ---------------------------------------------------------------------------
// Launch
// ---------------------------------------------------------------------------
extern "C" void kernel_launch(void* const* d_in, const int* in_sizes, int n_in,
                              void* d_out, int out_size)
{
    const float* x   = (const float*)d_in[0];
    const float* Wq  = (const float*)d_in[1];
    const float* Wk  = (const float*)d_in[2];
    const float* Wv  = (const float*)d_in[3];
    const float* Wo  = (const float*)d_in[4];
    const float* bo  = (const float*)d_in[5];
    const float* W1  = (const float*)d_in[6];
    const float* b1  = (const float*)d_in[7];
    const float* W2  = (const float*)d_in[8];
    const float* b2  = (const float*)d_in[9];
    const float* g1  = (const float*)d_in[10];
    const float* be1 = (const float*)d_in[11];
    const float* g2  = (const float*)d_in[12];
    const float* be2 = (const float*)d_in[13];
    float* out = (float*)d_out;

    half_t *xn, *qkv, *o, *xn2, *hb, *wqkv, *wo, *w1, *w2;
    float *x1;
    cudaGetSymbolAddress((void**)&xn,   g_xn);
    cudaGetSymbolAddress((void**)&qkv,  g_qkv);
    cudaGetSymbolAddress((void**)&o,    g_o);
    cudaGetSymbolAddress((void**)&x1,   g_x1);
    cudaGetSymbolAddress((void**)&xn2,  g_xn2);
    cudaGetSymbolAddress((void**)&hb,   g_h);
    cudaGetSymbolAddress((void**)&wqkv, g_wqkv);
    cudaGetSymbolAddress((void**)&wo,   g_wo);
    cudaGetSymbolAddress((void**)&w1,   g_w1);
    cudaGetSymbolAddress((void**)&w2,   g_w2);

    cudaFuncSetAttribute(mma_gemm_kernel<0>,
                         cudaFuncAttributeMaxDynamicSharedMemorySize, SMG_TOTAL);
    cudaFuncSetAttribute(mma_gemm_kernel<1>,
                         cudaFuncAttributeMaxDynamicSharedMemorySize, SMG_TOTAL);
    cudaFuncSetAttribute(mma_gemm_kernel<2>,
                         cudaFuncAttributeMaxDynamicSharedMemorySize, SMG_TOTAL);

    // all weight packing in one launch
    pack_all_kernel<<<(NW_TOT + 255) / 256, 256>>>(Wq, Wk, Wv, Wo, W1, W2,
                                                   wqkv, wo, w1, w2);

    // LN1
    ln_kernel<<<NROWS, 128>>>(x, g1, be1, xn);

    // QKV projection -> fp16
    mma_gemm_kernel<0><<<dim3(QKVW / 128, NROWS / 128), 256, SMG_TOTAL>>>(
        xn, wqkv, nullptr, qkv, CC, QKVW, nullptr, nullptr);

    // causal attention (tensor cores, double-buffered K/V)
    attn_kernel<<<dim3(4, HH, BB), 128>>>(qkv, o);

    // output projection + bias + residual -> f32
    mma_gemm_kernel<1><<<dim3(CC / 128, NROWS / 128), 256, SMG_TOTAL>>>(
        o, wo, x1, nullptr, CC, CC, bo, x);

    // LN2
    ln_kernel<<<NROWS, 128>>>(x1, g2, be2, xn2);

    // MLP up + ReLU -> fp16
    mma_gemm_kernel<2><<<dim3(FFN / 128, NROWS / 128), 256, SMG_TOTAL>>>(
        xn2, w1, nullptr, hb, CC, FFN, b1, nullptr);

    // MLP down + bias + residual -> out (f32)
    mma_gemm_kernel<1><<<dim3(CC / 128, NROWS / 128), 256, SMG_TOTAL>>>(
        hb, w2, out, nullptr, FFN, CC, b2, x1);
}